// round 11
// baseline (speedup 1.0000x reference)
#include <cuda_runtime.h>
#include <cuda_bf16.h>
#include <cstdint>

// Problem constants
#define NWIN 400
#define NTOK 324
#define NPAD 336
#define CE   128
#define CC   256
#define HH   180
#define WSZ  18

// ---- embed config (unchanged from R10) ----
#define EBR    48
#define NBLK_E 7
#define NTH    384
#define EMB_LD 264  // words 132, mod32=4

// ---- attn v2 config ----
#define NTH_A  192   // 6 warps, each owns 16 rows x all 336 cols
#define BLKR   96
#define TH_LD  136   // words 68, mod32=4
#define AV_LD  56    // words 28, mod32=28
#define AVK    48
#define PJ_LD2 136

// attn smem element offsets (bf16 elems)
#define N_PHI   (NPAD * TH_LD)           // 45696
#define OFF_TH  (N_PHI)                  // 45696
#define N_TH    (BLKR * TH_LD)           // 13056
#define OFF_AV0 (OFF_TH + N_TH)          // 58752
#define N_AVB   (CC * AV_LD)             // 14336
#define OFF_AV1 (OFF_AV0 + N_AVB)        // 73088
#define ATTN_SMEM ((OFF_AV1 + N_AVB) * 2)  // 174848 B
#define PB_HALF (128 * PJ_LD2)           // 17408 elems (proj chunk, overlays phi)

// ---------------- global scratch ----------------
__device__ __nv_bfloat16 g_embT [NWIN * NPAD * CC];  // [w][n][e]: e<128 theta, e>=128 phi
__device__ __nv_bfloat16 g_xw   [NWIN * CC * NPAD];  // [w][c][m]
__device__ __nv_bfloat16 g_wprojb[CC * CC];          // [o][c]

// ---------------- helpers ----------------
__device__ __forceinline__ uint32_t s2u(const __nv_bfloat16* p) {
    return (uint32_t)__cvta_generic_to_shared(p);
}
__device__ __forceinline__ void ldsm4(uint32_t& r0, uint32_t& r1, uint32_t& r2, uint32_t& r3,
                                      uint32_t a) {
    asm volatile("ldmatrix.sync.aligned.m8n8.x4.shared.b16 {%0,%1,%2,%3}, [%4];"
        : "=r"(r0), "=r"(r1), "=r"(r2), "=r"(r3) : "r"(a));
}
__device__ __forceinline__ void ldsm2(uint32_t& r0, uint32_t& r1, uint32_t a) {
    asm volatile("ldmatrix.sync.aligned.m8n8.x2.shared.b16 {%0,%1}, [%2];"
        : "=r"(r0), "=r"(r1) : "r"(a));
}
__device__ __forceinline__ void mma16816(float* c, uint32_t a0, uint32_t a1,
                                         uint32_t a2, uint32_t a3,
                                         uint32_t b0, uint32_t b1) {
    asm volatile(
        "mma.sync.aligned.m16n8k16.row.col.f32.bf16.bf16.f32 "
        "{%0,%1,%2,%3},{%4,%5,%6,%7},{%8,%9},{%0,%1,%2,%3};\n"
        : "+f"(c[0]), "+f"(c[1]), "+f"(c[2]), "+f"(c[3])
        : "r"(a0), "r"(a1), "r"(a2), "r"(a3), "r"(b0), "r"(b1));
}
__device__ __forceinline__ void st_bf2(__nv_bfloat16* p, float lo, float hi) {
    *reinterpret_cast<__nv_bfloat162*>(p) = __floats2bfloat162_rn(lo, hi);
}
__device__ __forceinline__ uint32_t pk2(float lo, float hi) {
    __nv_bfloat162 v = __floats2bfloat162_rn(lo, hi);
    return *reinterpret_cast<uint32_t*>(&v);
}
__device__ __forceinline__ void cp16(__nv_bfloat16* dst, const __nv_bfloat16* src) {
    *reinterpret_cast<uint4*>(dst) = *reinterpret_cast<const uint4*>(src);
}
__device__ __forceinline__ void cpasync16(__nv_bfloat16* smem_dst, const __nv_bfloat16* gsrc) {
    uint32_t s = (uint32_t)__cvta_generic_to_shared(smem_dst);
    asm volatile("cp.async.cg.shared.global [%0], [%1], 16;\n" :: "r"(s), "l"(gsrc));
}
#define CP_COMMIT() asm volatile("cp.async.commit_group;\n" ::: "memory")
#define CP_WAIT1()  asm volatile("cp.async.wait_group 1;\n" ::: "memory")
#define CP_WAIT0()  asm volatile("cp.async.wait_group 0;\n" ::: "memory")

// ---------------- kernel 1: window partition + embed GEMM (unchanged R10) ----
#define EMBED_SMEM ((CC * EMB_LD + 2 * EBR * EMB_LD) * 2)

__global__ __launch_bounds__(NTH, 1) void embed_kernel(const float* __restrict__ x,
                                                       const float* __restrict__ wt,
                                                       const float* __restrict__ wp,
                                                       const float* __restrict__ wproj) {
    extern __shared__ char smem_raw[];
    __nv_bfloat16* wcomb_s = reinterpret_cast<__nv_bfloat16*>(smem_raw);
    __nv_bfloat16* xb0 = wcomb_s + CC * EMB_LD;
    __nv_bfloat16* xb1 = xb0 + EBR * EMB_LD;

    int w = blockIdx.x;
    int b = w / 100, rem = w % 100, wh = rem / 10, ww = rem % 10;
    int h0 = wh * WSZ, w0 = ww * WSZ;
    const float* xb = x + (size_t)b * CC * HH * HH;
    int tid = threadIdx.x;
    int warp = tid >> 5, lane = tid & 31;
    int rw = warp >> 2, cw = warp & 3;
    int g = lane >> 2, q = lane & 3;
    int lA = lane & 15, kA = (lane >> 4) << 3;
    int lB = lane & 7,  kB = ((lane >> 3) & 1) << 3;

    if (blockIdx.x == 0) {
        for (int idx = tid; idx < CC * CC / 4; idx += NTH) {
            float4 f = *reinterpret_cast<const float4*>(&wproj[idx * 4]);
            __nv_bfloat162 lo = __floats2bfloat162_rn(f.x, f.y);
            __nv_bfloat162 hi = __floats2bfloat162_rn(f.z, f.w);
            uint2 v; v.x = *reinterpret_cast<uint32_t*>(&lo); v.y = *reinterpret_cast<uint32_t*>(&hi);
            *reinterpret_cast<uint2*>(&g_wprojb[idx * 4]) = v;
        }
    }

    for (int idx = tid; idx < CC * 64; idx += NTH) {
        int e = idx >> 6, v = idx & 63;
        const float* src = (e < CE) ? &wt[e * CC + v * 4] : &wp[(e - CE) * CC + v * 4];
        float4 f = *reinterpret_cast<const float4*>(src);
        __nv_bfloat162 lo = __floats2bfloat162_rn(f.x, f.y);
        __nv_bfloat162 hi = __floats2bfloat162_rn(f.z, f.w);
        uint2 o; o.x = *reinterpret_cast<uint32_t*>(&lo); o.y = *reinterpret_cast<uint32_t*>(&hi);
        *reinterpret_cast<uint2*>(&wcomb_s[e * EMB_LD + v * 4]) = o;
    }

    __nv_bfloat16* xwg  = g_xw   + (size_t)w * CC * NPAD;
    __nv_bfloat16* embT = g_embT + (size_t)w * NPAD * CC;

    #pragma unroll
    for (int it = 0; it < 32; it++) {
        int idx = tid + it * NTH;
        int nn = idx % EBR, c = idx / EBR;
        int m = nn;
        float v = (m < NTOK) ? xb[((size_t)c * HH + h0 + m / WSZ) * HH + w0 + m % WSZ] : 0.f;
        __nv_bfloat16 bv = __float2bfloat16(v);
        xb0[nn * EMB_LD + c] = bv;
        xwg[c * NPAD + m] = bv;
    }
    __syncthreads();

    uint32_t aAdr[2] = { s2u(&xb0[(rw * 16 + lA) * EMB_LD + kA]),
                         s2u(&xb1[(rw * 16 + lA) * EMB_LD + kA]) };
    uint32_t bAdr = s2u(&wcomb_s[(cw * 64 + lB) * EMB_LD + kB]);

    for (int blk = 0; blk < NBLK_E; blk++) {
        float vreg[32];
        if (blk + 1 < NBLK_E) {
            #pragma unroll
            for (int it = 0; it < 32; it++) {
                int idx = tid + it * NTH;
                int nn = idx % EBR, c = idx / EBR;
                int m = (blk + 1) * EBR + nn;
                vreg[it] = (m < NTOK) ? xb[((size_t)c * HH + h0 + m / WSZ) * HH + w0 + m % WSZ] : 0.f;
            }
        }

        float acc[8][4];
        #pragma unroll
        for (int t = 0; t < 8; t++) { acc[t][0]=0.f; acc[t][1]=0.f; acc[t][2]=0.f; acc[t][3]=0.f; }
        uint32_t aA = aAdr[blk & 1];
        #pragma unroll
        for (int kt = 0; kt < 16; kt++) {
            uint32_t a0, a1, a2, a3;
            ldsm4(a0, a1, a2, a3, aA + kt * 32);
            #pragma unroll
            for (int t = 0; t < 8; t++) {
                uint32_t b0, b1;
                ldsm2(b0, b1, bAdr + t * (8 * EMB_LD * 2) + kt * 32);
                mma16816(acc[t], a0, a1, a2, a3, b0, b1);
            }
        }
        {
            int r0 = blk * EBR + rw * 16 + g, r1 = r0 + 8;
            #pragma unroll
            for (int t = 0; t < 8; t++) {
                int e0 = cw * 64 + t * 8 + q * 2;
                st_bf2(&embT[r0 * CC + e0], acc[t][0], acc[t][1]);
                st_bf2(&embT[r1 * CC + e0], acc[t][2], acc[t][3]);
            }
        }
        if (blk + 1 < NBLK_E) {
            __nv_bfloat16* dst = (blk & 1) ? xb0 : xb1;
            #pragma unroll
            for (int it = 0; it < 32; it++) {
                int idx = tid + it * NTH;
                int nn = idx % EBR, c = idx / EBR;
                int m = (blk + 1) * EBR + nn;
                __nv_bfloat16 bv = __float2bfloat16(vreg[it]);
                dst[nn * EMB_LD + c] = bv;
                xwg[c * NPAD + m] = bv;
            }
        }
        __syncthreads();
    }
}

// ---------------- kernel 2: attn v2 — P and y register-resident ----------------
// grid = NWIN*4; CTA = one 96-row block of one window. 6 warps x 16 rows x 336 cols.
__global__ __launch_bounds__(NTH_A, 1) void attn_kernel(const float* __restrict__ x,
                                                        float* __restrict__ out) {
    extern __shared__ char smem_raw[];
    __nv_bfloat16* sm    = reinterpret_cast<__nv_bfloat16*>(smem_raw);
    __nv_bfloat16* phi_s = sm;                 // [336][TH_LD]; later proj chunks
    __nv_bfloat16* th_s  = sm + OFF_TH;        // [96][TH_LD]
    __nv_bfloat16* av0   = sm + OFF_AV0;       // [256][AV_LD]
    __nv_bfloat16* av1   = sm + OFF_AV1;
    __nv_bfloat16* pbuf0 = phi_s;              // [128][PJ_LD2] (phi dead by then)
    __nv_bfloat16* pbuf1 = phi_s + PB_HALF;
    float* out_s = reinterpret_cast<float*>(smem_raw + OFF_AV0 * 2);  // fp32 [96][129]

    int bid = blockIdx.x;
    int w = bid >> 2, blk = bid & 3;
    int b = w / 100, rem = w % 100, wh = rem / 10, ww = rem % 10;
    int h0 = wh * WSZ, w0 = ww * WSZ;
    int tid = threadIdx.x;
    int rw = tid >> 5, lane = tid & 31;
    int g = lane >> 2, q = lane & 3;
    int lA = lane & 15, kA = (lane >> 4) << 3;          // ldsm4 A pattern
    int lB8 = lane & 7, sel = (lane >> 3) & 1, nh = lane >> 4;  // ldsm4 B-pair pattern

    const __nv_bfloat16* embT = g_embT + (size_t)w * NPAD * CC;
    const __nv_bfloat16* xwg  = g_xw   + (size_t)w * CC * NPAD;

    const float scale = 0.08838834764831845f;  // 1/sqrt(128)

    // ---- stage: phi rows 0..175 + theta (group 1), phi rows 176..335 (group 2) ----
    for (int idx = tid; idx < 176 * 16; idx += NTH_A) {
        int r = idx >> 4, v = idx & 15;
        cpasync16(&phi_s[r * TH_LD + v * 8], &embT[r * CC + CE + v * 8]);
    }
    for (int idx = tid; idx < BLKR * 16; idx += NTH_A) {
        int r = idx >> 4, v = idx & 15;
        int ng = blk * BLKR + r;
        if (ng < NPAD) cpasync16(&th_s[r * TH_LD + v * 8], &embT[ng * CC + v * 8]);
        else *reinterpret_cast<uint4*>(&th_s[r * TH_LD + v * 8]) = make_uint4(0,0,0,0);
    }
    CP_COMMIT();
    for (int idx = tid; idx < 160 * 16; idx += NTH_A) {
        int r = 176 + (idx >> 4), v = idx & 15;
        cpasync16(&phi_s[r * TH_LD + v * 8], &embT[r * CC + CE + v * 8]);
    }
    CP_COMMIT();

    uint32_t aTh = s2u(&th_s[(rw * 16 + lA) * TH_LD + kA]);
    uint32_t bPhi = s2u(&phi_s[(nh * 8 + lB8) * TH_LD + sel * 8]);

    // ---- S = theta @ phi^T, full 336 cols per warp, in registers ----
    float sacc[42][4];
    #pragma unroll
    for (int t = 0; t < 42; t++) { sacc[t][0]=0.f; sacc[t][1]=0.f; sacc[t][2]=0.f; sacc[t][3]=0.f; }

    CP_WAIT1();
    __syncthreads();
    #pragma unroll
    for (int kt = 0; kt < 8; kt++) {
        uint32_t a0, a1, a2, a3;
        ldsm4(a0, a1, a2, a3, aTh + kt * 32);
        #pragma unroll
        for (int p = 0; p < 11; p++) {
            uint32_t b0, b1, b2, b3;
            ldsm4(b0, b1, b2, b3, bPhi + (p * 16 * TH_LD + kt * 16) * 2);
            mma16816(sacc[2*p],   a0, a1, a2, a3, b0, b1);
            mma16816(sacc[2*p+1], a0, a1, a2, a3, b2, b3);
        }
    }
    CP_WAIT0();
    __syncthreads();
    #pragma unroll
    for (int kt = 0; kt < 8; kt++) {
        uint32_t a0, a1, a2, a3;
        ldsm4(a0, a1, a2, a3, aTh + kt * 32);
        #pragma unroll
        for (int p = 11; p < 21; p++) {
            uint32_t b0, b1, b2, b3;
            ldsm4(b0, b1, b2, b3, bPhi + (p * 16 * TH_LD + kt * 16) * 2);
            mma16816(sacc[2*p],   a0, a1, a2, a3, b0, b1);
            mma16816(sacc[2*p+1], a0, a1, a2, a3, b2, b3);
        }
    }

    // ---- softmax (registers + shuffles only; rows fully within warp) ----
    #pragma unroll
    for (int t = 0; t < 42; t++) {
        int c0 = t * 8 + q * 2;
        #pragma unroll
        for (int i = 0; i < 4; i++) {
            float v = sacc[t][i] * scale;
            if (c0 + (i & 1) >= NTOK) v = -1e30f;
            sacc[t][i] = v;
        }
    }
    float m0 = -1e30f, m1 = -1e30f;
    #pragma unroll
    for (int t = 0; t < 42; t++) {
        m0 = fmaxf(m0, fmaxf(sacc[t][0], sacc[t][1]));
        m1 = fmaxf(m1, fmaxf(sacc[t][2], sacc[t][3]));
    }
    m0 = fmaxf(m0, __shfl_xor_sync(0xffffffffu, m0, 1));
    m0 = fmaxf(m0, __shfl_xor_sync(0xffffffffu, m0, 2));
    m1 = fmaxf(m1, __shfl_xor_sync(0xffffffffu, m1, 1));
    m1 = fmaxf(m1, __shfl_xor_sync(0xffffffffu, m1, 2));
    float s0 = 0.f, s1 = 0.f;
    #pragma unroll
    for (int t = 0; t < 42; t++) {
        sacc[t][0] = __expf(sacc[t][0] - m0);
        sacc[t][1] = __expf(sacc[t][1] - m0);
        sacc[t][2] = __expf(sacc[t][2] - m1);
        sacc[t][3] = __expf(sacc[t][3] - m1);
        s0 += sacc[t][0] + sacc[t][1];
        s1 += sacc[t][2] + sacc[t][3];
    }
    s0 += __shfl_xor_sync(0xffffffffu, s0, 1);
    s0 += __shfl_xor_sync(0xffffffffu, s0, 2);
    s1 += __shfl_xor_sync(0xffffffffu, s1, 1);
    s1 += __shfl_xor_sync(0xffffffffu, s1, 2);
    float inv0 = 1.f / s0, inv1 = 1.f / s1;

    // ---- pack P into AV A-fragments (C-frag layout == A-frag layout) ----
    uint32_t pA[21][4];
    #pragma unroll
    for (int kt = 0; kt < 21; kt++) {
        pA[kt][0] = pk2(sacc[2*kt][0]   * inv0, sacc[2*kt][1]   * inv0);
        pA[kt][1] = pk2(sacc[2*kt][2]   * inv1, sacc[2*kt][3]   * inv1);
        pA[kt][2] = pk2(sacc[2*kt+1][0] * inv0, sacc[2*kt+1][1] * inv0);
        pA[kt][3] = pk2(sacc[2*kt+1][2] * inv1, sacc[2*kt+1][3] * inv1);
    }

    // ---- AV: y = P @ xw^T, 7 double-buffered chunks of 48; y in registers ----
    // prologue: chunk 0
    for (int idx = tid; idx < CC * (AVK / 8); idx += NTH_A) {
        int c = idx / (AVK / 8), v = idx % (AVK / 8);
        cpasync16(&av0[c * AV_LD + v * 8], &xwg[c * NPAD + v * 8]);
    }
    CP_COMMIT();
    __syncthreads();   // S done: phi region free from here

    uint32_t bAvP[2] = { s2u(&av0[(nh * 8 + lB8) * AV_LD + sel * 8]),
                         s2u(&av1[(nh * 8 + lB8) * AV_LD + sel * 8]) };

    float yacc[32][4];
    #pragma unroll
    for (int t = 0; t < 32; t++) { yacc[t][0]=0.f; yacc[t][1]=0.f; yacc[t][2]=0.f; yacc[t][3]=0.f; }

    for (int mc = 0; mc < 7; mc++) {
        if (mc < 6) {
            __nv_bfloat16* nb = ((mc + 1) & 1) ? av1 : av0;
            for (int idx = tid; idx < CC * (AVK / 8); idx += NTH_A) {
                int c = idx / (AVK / 8), v = idx % (AVK / 8);
                cpasync16(&nb[c * AV_LD + v * 8], &xwg[c * NPAD + (mc + 1) * AVK + v * 8]);
            }
            if (mc == 0) {
                // prefetch proj stage0 (h0,k0) into pbuf0 (phi region, now free)
                for (int idx = tid; idx < 128 * 16; idx += NTH_A) {
                    int o = idx >> 4, v = idx & 15;
                    cpasync16(&pbuf0[o * PJ_LD2 + v * 8], &g_wprojb[o * CC + v * 8]);
                }
            }
            CP_COMMIT();
            CP_WAIT1();
        } else {
            CP_WAIT0();
        }
        __syncthreads();
        uint32_t bAv = bAvP[mc & 1];
        #pragma unroll
        for (int kt = 0; kt < 3; kt++) {
            int gk = mc * 3 + kt;
            uint32_t a0 = pA[gk][0], a1 = pA[gk][1], a2 = pA[gk][2], a3 = pA[gk][3];
            #pragma unroll
            for (int p = 0; p < 16; p++) {
                uint32_t b0, b1, b2, b3;
                ldsm4(b0, b1, b2, b3, bAv + (p * 16 * AV_LD + kt * 16) * 2);
                mma16816(yacc[2*p],   a0, a1, a2, a3, b0, b1);
                mma16816(yacc[2*p+1], a0, a1, a2, a3, b2, b3);
            }
        }
        __syncthreads();
    }

    // ---- pack y into proj A-fragments ----
    uint32_t pY[16][4];
    #pragma unroll
    for (int kt = 0; kt < 16; kt++) {
        pY[kt][0] = pk2(yacc[2*kt][0],   yacc[2*kt][1]);
        pY[kt][1] = pk2(yacc[2*kt][2],   yacc[2*kt][3]);
        pY[kt][2] = pk2(yacc[2*kt+1][0], yacc[2*kt+1][1]);
        pY[kt][3] = pk2(yacc[2*kt+1][2], yacc[2*kt+1][3]);
    }

    // ---- proj: out = y @ wproj^T; stages (h,kc): s0=(0,0) s1=(0,1) s2=(1,0) s3=(1,1) ----
    uint32_t bPjP[2] = { s2u(&pbuf0[(nh * 8 + lB8) * PJ_LD2 + sel * 8]),
                         s2u(&pbuf1[(nh * 8 + lB8) * PJ_LD2 + sel * 8]) };
    // prologue: stage 1 -> pbuf1
    for (int idx = tid; idx < 128 * 16; idx += NTH_A) {
        int o = idx >> 4, v = idx & 15;
        cpasync16(&pbuf1[o * PJ_LD2 + v * 8], &g_wprojb[o * CC + 128 + v * 8]);
    }
    CP_COMMIT();

    float pacc[16][4];
    #pragma unroll
    for (int t = 0; t < 16; t++) { pacc[t][0]=0.f; pacc[t][1]=0.f; pacc[t][2]=0.f; pacc[t][3]=0.f; }

    for (int s = 0; s < 4; s++) {
        if (s < 3) {
            if (s >= 1) {
                __nv_bfloat16* nb = ((s + 1) & 1) ? pbuf1 : pbuf0;
                int h = (s + 1) >> 1, kc = (s + 1) & 1;
                for (int idx = tid; idx < 128 * 16; idx += NTH_A) {
                    int o = idx >> 4, v = idx & 15;
                    cpasync16(&nb[o * PJ_LD2 + v * 8],
                              &g_wprojb[(h * 128 + o) * CC + kc * 128 + v * 8]);
                }
                CP_COMMIT();
            }
            CP_WAIT1();
        } else {
            CP_WAIT0();
        }
        __syncthreads();
        int kc = s & 1;
        uint32_t bPj = bPjP[s & 1];
        #pragma unroll
        for (int kt = 0; kt < 8; kt++) {
            int gk = kc * 8 + kt;
            uint32_t a0 = pY[gk][0], a1 = pY[gk][1], a2 = pY[gk][2], a3 = pY[gk][3];
            #pragma unroll
            for (int p = 0; p < 8; p++) {
                uint32_t b0, b1, b2, b3;
                ldsm4(b0, b1, b2, b3, bPj + (p * 16 * PJ_LD2 + kt * 16) * 2);
                mma16816(pacc[2*p],   a0, a1, a2, a3, b0, b1);
                mma16816(pacc[2*p+1], a0, a1, a2, a3, b2, b3);
            }
        }
        __syncthreads();

        if (s == 1 || s == 3) {
            // ---- epilogue for o-half h = s>>1: transpose via out_s, residual, write ----
            int h = s >> 1;
            int lr0 = rw * 16 + g, lr1 = lr0 + 8;
            #pragma unroll
            for (int t = 0; t < 16; t++) {
                int cc = t * 8 + q * 2;
                out_s[lr0 * 129 + cc]     = pacc[t][0];
                out_s[lr0 * 129 + cc + 1] = pacc[t][1];
                out_s[lr1 * 129 + cc]     = pacc[t][2];
                out_s[lr1 * 129 + cc + 1] = pacc[t][3];
            }
            __syncthreads();
            for (int idx = tid; idx < BLKR * 128; idx += NTH_A) {
                int nl = idx % BLKR, ol = idx / BLKR;
                int ng = blk * BLKR + nl;
                if (ng < NTOK) {
                    int o = h * 128 + ol;
                    int i = ng / WSZ, j = ng - i * WSZ;
                    size_t gi = ((size_t)(b * CC + o) * HH + h0 + i) * HH + w0 + j;
                    out[gi] = x[gi] + out_s[nl * 129 + ol];
                }
            }
            __syncthreads();
            if (s == 1) {
                #pragma unroll
                for (int t = 0; t < 16; t++) { pacc[t][0]=0.f; pacc[t][1]=0.f; pacc[t][2]=0.f; pacc[t][3]=0.f; }
            }
        }
    }
}

// ---------------- launch ----------------
extern "C" void kernel_launch(void* const* d_in, const int* in_sizes, int n_in,
                              void* d_out, int out_size) {
    const float* x     = (const float*)d_in[0];
    const float* wt    = (const float*)d_in[1];
    const float* wp    = (const float*)d_in[2];
    const float* wproj = (const float*)d_in[3];
    float* out = (float*)d_out;

    cudaFuncSetAttribute(embed_kernel, cudaFuncAttributeMaxDynamicSharedMemorySize, EMBED_SMEM);
    cudaFuncSetAttribute(attn_kernel,  cudaFuncAttributeMaxDynamicSharedMemorySize, ATTN_SMEM);

    embed_kernel<<<NWIN, NTH, EMBED_SMEM>>>(x, wt, wp, wproj);
    attn_kernel<<<NWIN * 4, NTH_A, ATTN_SMEM>>>(x, out);
}

// round 14
// speedup vs baseline: 1.2748x; 1.2748x over previous
#include <cuda_runtime.h>
#include <cuda_bf16.h>
#include <cstdint>

// Problem constants
#define NWIN 400
#define NTOK 324
#define NPAD 336    // 3 * 112, 7 * 48
#define CE   128
#define CC   256
#define HH   180
#define WSZ  18

#define BLKR  96    // attn token rows per block
#define NBLK  4
#define SCH   112   // S phi m-chunk
#define AVK   48    // AV k-chunk
#define NTH   384   // threads

#define EBR   48    // embed token rows per block
#define NBLK_E 7

// smem leading dims (elements); ldmatrix 8-row wavefronts cover all 32 banks
#define EMB_LD 264  // words 132, mod32=4
#define TH_LD  136  // words 68,  mod32=4
#define P_LD   344  // words 172, mod32=12
#define AV_LD  56   // words 28,  mod32=28
#define PJ_LD  136  // words 68,  mod32=4

// per-half ping-pong buffer; 2*CHUNK_HALF holds proj staging [256][PJ_LD]=34816
// and epilogue fp32 [96][129]
#define CHUNK_HALF 17408

// ---------------- global scratch ----------------
__device__ __nv_bfloat16 g_embT [NWIN * NPAD * CC];  // [w][n][e]: e<128 theta, e>=128 phi
__device__ __nv_bfloat16 g_xw   [NWIN * CC * NPAD];  // [w][c][m]
__device__ __nv_bfloat16 g_wprojb[CC * CC];          // [o][c] (written by embed block 0)

// ---------------- helpers ----------------
__device__ __forceinline__ uint32_t s2u(const __nv_bfloat16* p) {
    return (uint32_t)__cvta_generic_to_shared(p);
}
__device__ __forceinline__ void ldsm4(uint32_t& r0, uint32_t& r1, uint32_t& r2, uint32_t& r3,
                                      uint32_t a) {
    asm volatile("ldmatrix.sync.aligned.m8n8.x4.shared.b16 {%0,%1,%2,%3}, [%4];"
        : "=r"(r0), "=r"(r1), "=r"(r2), "=r"(r3) : "r"(a));
}
__device__ __forceinline__ void ldsm2(uint32_t& r0, uint32_t& r1, uint32_t a) {
    asm volatile("ldmatrix.sync.aligned.m8n8.x2.shared.b16 {%0,%1}, [%2];"
        : "=r"(r0), "=r"(r1) : "r"(a));
}
__device__ __forceinline__ void mma16816(float* c, uint32_t a0, uint32_t a1,
                                         uint32_t a2, uint32_t a3,
                                         uint32_t b0, uint32_t b1) {
    asm volatile(
        "mma.sync.aligned.m16n8k16.row.col.f32.bf16.bf16.f32 "
        "{%0,%1,%2,%3},{%4,%5,%6,%7},{%8,%9},{%0,%1,%2,%3};\n"
        : "+f"(c[0]), "+f"(c[1]), "+f"(c[2]), "+f"(c[3])
        : "r"(a0), "r"(a1), "r"(a2), "r"(a3), "r"(b0), "r"(b1));
}
__device__ __forceinline__ void st_bf2(__nv_bfloat16* p, float lo, float hi) {
    *reinterpret_cast<__nv_bfloat162*>(p) = __floats2bfloat162_rn(lo, hi);
}
__device__ __forceinline__ void cp16(__nv_bfloat16* dst, const __nv_bfloat16* src) {
    *reinterpret_cast<uint4*>(dst) = *reinterpret_cast<const uint4*>(src);
}
__device__ __forceinline__ void cpasync16(__nv_bfloat16* smem_dst, const __nv_bfloat16* gsrc) {
    uint32_t s = (uint32_t)__cvta_generic_to_shared(smem_dst);
    asm volatile("cp.async.cg.shared.global [%0], [%1], 16;\n" :: "r"(s), "l"(gsrc));
}
#define CP_COMMIT() asm volatile("cp.async.commit_group;\n" ::: "memory")
#define CP_WAIT1()  asm volatile("cp.async.wait_group 1;\n" ::: "memory")
#define CP_WAIT0()  asm volatile("cp.async.wait_group 0;\n" ::: "memory")

// ---------------- kernel 1: window partition + embed GEMM (also preps wproj) ----
#define EMBED_SMEM ((CC * EMB_LD + 2 * EBR * EMB_LD) * 2)

__global__ __launch_bounds__(NTH, 1) void embed_kernel(const float* __restrict__ x,
                                                       const float* __restrict__ wt,
                                                       const float* __restrict__ wp,
                                                       const float* __restrict__ wproj) {
    extern __shared__ char smem_raw[];
    __nv_bfloat16* wcomb_s = reinterpret_cast<__nv_bfloat16*>(smem_raw);
    __nv_bfloat16* xb0 = wcomb_s + CC * EMB_LD;
    __nv_bfloat16* xb1 = xb0 + EBR * EMB_LD;

    int w = blockIdx.x;
    int b = w / 100, rem = w % 100, wh = rem / 10, ww = rem % 10;
    int h0 = wh * WSZ, w0 = ww * WSZ;
    const float* xb = x + (size_t)b * CC * HH * HH;
    int tid = threadIdx.x;
    int warp = tid >> 5, lane = tid & 31;
    int rw = warp >> 2, cw = warp & 3;   // 3 row-groups x 4 col-quarters
    int g = lane >> 2, q = lane & 3;
    int lA = lane & 15, kA = (lane >> 4) << 3;                 // ldsm4 A pattern
    int lB8 = lane & 7, sel = (lane >> 3) & 1, nh = lane >> 4; // ldsm4 B-pair pattern

    if (blockIdx.x == 0) {
        for (int idx = tid; idx < CC * CC / 4; idx += NTH) {
            float4 f = *reinterpret_cast<const float4*>(&wproj[idx * 4]);
            __nv_bfloat162 lo = __floats2bfloat162_rn(f.x, f.y);
            __nv_bfloat162 hi = __floats2bfloat162_rn(f.z, f.w);
            uint2 v; v.x = *reinterpret_cast<uint32_t*>(&lo); v.y = *reinterpret_cast<uint32_t*>(&hi);
            *reinterpret_cast<uint2*>(&g_wprojb[idx * 4]) = v;
        }
    }

    for (int idx = tid; idx < CC * 64; idx += NTH) {
        int e = idx >> 6, v = idx & 63;
        const float* src = (e < CE) ? &wt[e * CC + v * 4] : &wp[(e - CE) * CC + v * 4];
        float4 f = *reinterpret_cast<const float4*>(src);
        __nv_bfloat162 lo = __floats2bfloat162_rn(f.x, f.y);
        __nv_bfloat162 hi = __floats2bfloat162_rn(f.z, f.w);
        uint2 o; o.x = *reinterpret_cast<uint32_t*>(&lo); o.y = *reinterpret_cast<uint32_t*>(&hi);
        *reinterpret_cast<uint2*>(&wcomb_s[e * EMB_LD + v * 4]) = o;
    }

    __nv_bfloat16* xwg  = g_xw   + (size_t)w * CC * NPAD;
    __nv_bfloat16* embT = g_embT + (size_t)w * NPAD * CC;

    #pragma unroll
    for (int it = 0; it < 32; it++) {
        int idx = tid + it * NTH;
        int nn = idx % EBR, c = idx / EBR;
        int m = nn;
        float v = (m < NTOK) ? xb[((size_t)c * HH + h0 + m / WSZ) * HH + w0 + m % WSZ] : 0.f;
        __nv_bfloat16 bv = __float2bfloat16(v);
        xb0[nn * EMB_LD + c] = bv;
        xwg[c * NPAD + m] = bv;
    }
    __syncthreads();

    uint32_t aAdr[2] = { s2u(&xb0[(rw * 16 + lA) * EMB_LD + kA]),
                         s2u(&xb1[(rw * 16 + lA) * EMB_LD + kA]) };
    uint32_t bAdrP = s2u(&wcomb_s[(cw * 64 + nh * 8 + lB8) * EMB_LD + sel * 8]);

    for (int blk = 0; blk < NBLK_E; blk++) {
        float vreg[32];
        if (blk + 1 < NBLK_E) {
            #pragma unroll
            for (int it = 0; it < 32; it++) {
                int idx = tid + it * NTH;
                int nn = idx % EBR, c = idx / EBR;
                int m = (blk + 1) * EBR + nn;
                vreg[it] = (m < NTOK) ? xb[((size_t)c * HH + h0 + m / WSZ) * HH + w0 + m % WSZ] : 0.f;
            }
        }

        float acc[8][4];
        #pragma unroll
        for (int t = 0; t < 8; t++) { acc[t][0]=0.f; acc[t][1]=0.f; acc[t][2]=0.f; acc[t][3]=0.f; }
        uint32_t aA = aAdr[blk & 1];
        #pragma unroll
        for (int kt = 0; kt < 16; kt++) {
            uint32_t a0, a1, a2, a3;
            ldsm4(a0, a1, a2, a3, aA + kt * 32);
            #pragma unroll
            for (int p = 0; p < 4; p++) {
                uint32_t b0, b1, b2, b3;
                ldsm4(b0, b1, b2, b3, bAdrP + (p * 16 * EMB_LD + kt * 16) * 2);
                mma16816(acc[2*p],   a0, a1, a2, a3, b0, b1);
                mma16816(acc[2*p+1], a0, a1, a2, a3, b2, b3);
            }
        }
        {
            int r0 = blk * EBR + rw * 16 + g, r1 = r0 + 8;
            #pragma unroll
            for (int t = 0; t < 8; t++) {
                int e0 = cw * 64 + t * 8 + q * 2;
                st_bf2(&embT[r0 * CC + e0], acc[t][0], acc[t][1]);
                st_bf2(&embT[r1 * CC + e0], acc[t][2], acc[t][3]);
            }
        }
        if (blk + 1 < NBLK_E) {
            __nv_bfloat16* dst = (blk & 1) ? xb0 : xb1;
            #pragma unroll
            for (int it = 0; it < 32; it++) {
                int idx = tid + it * NTH;
                int nn = idx % EBR, c = idx / EBR;
                int m = (blk + 1) * EBR + nn;
                __nv_bfloat16 bv = __float2bfloat16(vreg[it]);
                dst[nn * EMB_LD + c] = bv;
                xwg[c * NPAD + m] = bv;
            }
        }
        __syncthreads();
    }
}

// ---------------- kernel 2: fused attention + projection + residual ----------------
#define ATTN_SMEM ((BLKR*TH_LD + BLKR*P_LD + BLKR*EMB_LD + 2*CHUNK_HALF) * 2 + BLKR*2*4*2)

__global__ __launch_bounds__(NTH, 1) void attn_kernel(const float* __restrict__ x,
                                                      float* __restrict__ out) {
    extern __shared__ char smem_raw[];
    __nv_bfloat16* th_s  = reinterpret_cast<__nv_bfloat16*>(smem_raw);   // [n][e]
    __nv_bfloat16* P_s   = th_s + BLKR * TH_LD;                          // [n][m]
    __nv_bfloat16* y_s   = P_s + BLKR * P_LD;                            // [n][c]
    __nv_bfloat16* chunk = y_s + BLKR * EMB_LD;                          // 2 x CHUNK_HALF
    float* stats_max = reinterpret_cast<float*>(chunk + 2 * CHUNK_HALF);
    float* stats_sum = stats_max + BLKR * 2;
    float* out_s = reinterpret_cast<float*>(chunk);                      // fp32 [96][129]

    __nv_bfloat16* buf[2] = {chunk, chunk + CHUNK_HALF};

    int w = blockIdx.x;
    int b = w / 100, rem = w % 100, wh = rem / 10, ww = rem % 10;
    int h0 = wh * WSZ, w0 = ww * WSZ;
    int tid = threadIdx.x;
    int warp = tid >> 5, lane = tid & 31;
    int rw = warp >> 1, cw = warp & 1;   // 6 x 2
    int g = lane >> 2, q = lane & 3;
    int lA = lane & 15, kA = (lane >> 4) << 3;
    int lB8 = lane & 7, sel = (lane >> 3) & 1, nh = lane >> 4;

    const __nv_bfloat16* embT = g_embT + (size_t)w * NPAD * CC;
    const __nv_bfloat16* xwg  = g_xw   + (size_t)w * CC * NPAD;

    const float scale = 0.08838834764831845f;  // 1/sqrt(128)

    // ldmatrix bases
    uint32_t aTh  = s2u(&th_s[(rw * 16 + lA) * TH_LD + kA]);
    uint32_t aP   = s2u(&P_s[(rw * 16 + lA) * P_LD + kA]);
    uint32_t aY   = s2u(&y_s[(rw * 16 + lA) * EMB_LD + kA]);
    // B-pair bases (ldsm4 over two adjacent n-tiles)
    uint32_t bPhiP[2] = { s2u(&buf[0][(cw * 56 + nh * 8 + lB8) * TH_LD + sel * 8]),
                          s2u(&buf[1][(cw * 56 + nh * 8 + lB8) * TH_LD + sel * 8]) };
    // single-tile base for S tile 6 (ldsm2 uses lanes 0-15 addresses)
    uint32_t bPhiS[2] = { s2u(&buf[0][(cw * 56 + 48 + lB8) * TH_LD + sel * 8]),
                          s2u(&buf[1][(cw * 56 + 48 + lB8) * TH_LD + sel * 8]) };
    uint32_t bAvP[2] = { s2u(&buf[0][(cw * 128 + nh * 8 + lB8) * AV_LD + sel * 8]),
                         s2u(&buf[1][(cw * 128 + nh * 8 + lB8) * AV_LD + sel * 8]) };
    uint32_t bPjP = s2u(&chunk[(cw * 128 + nh * 8 + lB8) * PJ_LD + sel * 8]);

    // strength-reduced staging constants (NTH=384: 384=64*6=4*96; multiples of 16)
    int v6 = tid % 6, c6 = tid / 6;          // AV staging: 4 iters, c += 64
    int nl = tid % 96, olb = tid / 96;       // epilogue: 32 iters, ol += 4

    for (int blk = 0; blk < NBLK; blk++) {
        // epilogue per-thread precompute for this blk
        int ng = blk * BLKR + nl;
        bool evalid = (ng < NTOK);
        size_t ebase = 0;
        if (evalid) {
            int i = ng / WSZ, j = ng - i * WSZ;
            ebase = ((size_t)b * CC * HH + h0 + i) * HH + w0 + j;
        }

        // ---- prefetch phi chunk 0 (async), then stage theta rows ----
        for (int idx = tid; idx < SCH * 16; idx += NTH) {
            int mm = idx >> 4, v = idx & 15;
            cpasync16(&buf[0][mm * TH_LD + v * 8], &embT[mm * CC + CE + v * 8]);
        }
        CP_COMMIT();
        for (int idx = tid; idx < BLKR * 16; idx += NTH) {
            int r = idx >> 4, v = idx & 15;
            int nr = blk * BLKR + r;
            if (nr < NPAD) cp16(&th_s[r * TH_LD + v * 8], &embT[nr * CC + v * 8]);
            else *reinterpret_cast<uint4*>(&th_s[r * TH_LD + v * 8]) = make_uint4(0,0,0,0);
        }

        // ---- S = theta_blk @ phi^T (96x336), k=128, 3 double-buffered chunks ----
        float sacc[21][4];
        #pragma unroll
        for (int t = 0; t < 21; t++) { sacc[t][0]=0.f; sacc[t][1]=0.f; sacc[t][2]=0.f; sacc[t][3]=0.f; }
        for (int mc = 0; mc < 3; mc++) {
            if (mc < 2) {
                for (int idx = tid; idx < SCH * 16; idx += NTH) {
                    int mm = idx >> 4, v = idx & 15;
                    cpasync16(&buf[(mc + 1) & 1][mm * TH_LD + v * 8],
                              &embT[((mc + 1) * SCH + mm) * CC + CE + v * 8]);
                }
                CP_COMMIT();
                CP_WAIT1();
            } else {
                CP_WAIT0();
            }
            __syncthreads();
            uint32_t bP = bPhiP[mc & 1], bS = bPhiS[mc & 1];
            #pragma unroll
            for (int kt = 0; kt < 8; kt++) {
                uint32_t a0, a1, a2, a3;
                ldsm4(a0, a1, a2, a3, aTh + kt * 32);
                #pragma unroll
                for (int p = 0; p < 3; p++) {
                    uint32_t b0, b1, b2, b3;
                    ldsm4(b0, b1, b2, b3, bP + (p * 16 * TH_LD + kt * 16) * 2);
                    mma16816(sacc[mc * 7 + 2*p],   a0, a1, a2, a3, b0, b1);
                    mma16816(sacc[mc * 7 + 2*p+1], a0, a1, a2, a3, b2, b3);
                }
                {
                    uint32_t b0, b1;
                    ldsm2(b0, b1, bS + kt * 32);
                    mma16816(sacc[mc * 7 + 6], a0, a1, a2, a3, b0, b1);
                }
            }
            __syncthreads();
        }
        // ---- scale + column mask ----
        #pragma unroll
        for (int mc = 0; mc < 3; mc++) {
            #pragma unroll
            for (int t = 0; t < 7; t++) {
                int c0 = mc * SCH + cw * 56 + t * 8 + q * 2;
                float* sv = sacc[mc * 7 + t];
                #pragma unroll
                for (int i = 0; i < 4; i++) {
                    float v = sv[i] * scale;
                    int col = c0 + (i & 1);
                    if (col >= NTOK) v = -1e30f;
                    sv[i] = v;
                }
            }
        }
        // ---- row max ----
        float m0 = -1e30f, m1 = -1e30f;
        #pragma unroll
        for (int t = 0; t < 21; t++) {
            m0 = fmaxf(m0, fmaxf(sacc[t][0], sacc[t][1]));
            m1 = fmaxf(m1, fmaxf(sacc[t][2], sacc[t][3]));
        }
        m0 = fmaxf(m0, __shfl_xor_sync(0xffffffffu, m0, 1));
        m0 = fmaxf(m0, __shfl_xor_sync(0xffffffffu, m0, 2));
        m1 = fmaxf(m1, __shfl_xor_sync(0xffffffffu, m1, 1));
        m1 = fmaxf(m1, __shfl_xor_sync(0xffffffffu, m1, 2));
        int row0 = rw * 16 + g, row1 = row0 + 8;
        if (q == 0) { stats_max[row0 * 2 + cw] = m0; stats_max[row1 * 2 + cw] = m1; }
        __syncthreads();
        float rmax0 = fmaxf(stats_max[row0 * 2], stats_max[row0 * 2 + 1]);
        float rmax1 = fmaxf(stats_max[row1 * 2], stats_max[row1 * 2 + 1]);
        // ---- exp + row sums ----
        float s0 = 0.f, s1 = 0.f;
        #pragma unroll
        for (int t = 0; t < 21; t++) {
            sacc[t][0] = __expf(sacc[t][0] - rmax0);
            sacc[t][1] = __expf(sacc[t][1] - rmax0);
            sacc[t][2] = __expf(sacc[t][2] - rmax1);
            sacc[t][3] = __expf(sacc[t][3] - rmax1);
            s0 += sacc[t][0] + sacc[t][1];
            s1 += sacc[t][2] + sacc[t][3];
        }
        s0 += __shfl_xor_sync(0xffffffffu, s0, 1);
        s0 += __shfl_xor_sync(0xffffffffu, s0, 2);
        s1 += __shfl_xor_sync(0xffffffffu, s1, 1);
        s1 += __shfl_xor_sync(0xffffffffu, s1, 2);
        if (q == 0) { stats_sum[row0 * 2 + cw] = s0; stats_sum[row1 * 2 + cw] = s1; }
        __syncthreads();
        float inv0 = 1.f / (stats_sum[row0 * 2] + stats_sum[row0 * 2 + 1]);
        float inv1 = 1.f / (stats_sum[row1 * 2] + stats_sum[row1 * 2 + 1]);
        // ---- write normalized P ----
        #pragma unroll
        for (int mc = 0; mc < 3; mc++) {
            #pragma unroll
            for (int t = 0; t < 7; t++) {
                int c0 = mc * SCH + cw * 56 + t * 8 + q * 2;
                float* sv = sacc[mc * 7 + t];
                st_bf2(&P_s[row0 * P_LD + c0], sv[0] * inv0, sv[1] * inv0);
                st_bf2(&P_s[row1 * P_LD + c0], sv[2] * inv1, sv[3] * inv1);
            }
        }
        // prefetch AV chunk 0 (async, strength-reduced); loop's first barrier publishes P_s
        {
            const __nv_bfloat16* src = xwg + c6 * NPAD + v6 * 8;
            __nv_bfloat16* dst = buf[0] + c6 * AV_LD + v6 * 8;
            #pragma unroll
            for (int it = 0; it < 4; it++)
                cpasync16(dst + it * 64 * AV_LD, src + it * 64 * NPAD);
        }
        CP_COMMIT();

        // ---- y = P @ xw^T (96x256), k=336 in 7 double-buffered chunks of 48 ----
        float yacc[16][4];
        #pragma unroll
        for (int t = 0; t < 16; t++) { yacc[t][0]=0.f; yacc[t][1]=0.f; yacc[t][2]=0.f; yacc[t][3]=0.f; }
        for (int mc = 0; mc < 7; mc++) {
            if (mc < 6) {
                const __nv_bfloat16* src = xwg + c6 * NPAD + (mc + 1) * AVK + v6 * 8;
                __nv_bfloat16* dst = buf[(mc + 1) & 1] + c6 * AV_LD + v6 * 8;
                #pragma unroll
                for (int it = 0; it < 4; it++)
                    cpasync16(dst + it * 64 * AV_LD, src + it * 64 * NPAD);
                CP_COMMIT();
                CP_WAIT1();
            } else {
                CP_WAIT0();
            }
            __syncthreads();
            uint32_t bAv = bAvP[mc & 1];
            #pragma unroll
            for (int kt = 0; kt < 3; kt++) {
                uint32_t a0, a1, a2, a3;
                ldsm4(a0, a1, a2, a3, aP + (mc * AVK + kt * 16) * 2);
                #pragma unroll
                for (int p = 0; p < 8; p++) {
                    uint32_t b0, b1, b2, b3;
                    ldsm4(b0, b1, b2, b3, bAv + (p * 16 * AV_LD + kt * 16) * 2);
                    mma16816(yacc[2*p],   a0, a1, a2, a3, b0, b1);
                    mma16816(yacc[2*p+1], a0, a1, a2, a3, b2, b3);
                }
            }
            __syncthreads();
        }
        // ---- stage y (bf16) ----
        {
            int r0 = rw * 16 + g, r1 = r0 + 8;
            #pragma unroll
            for (int t = 0; t < 16; t++) {
                int c0 = cw * 128 + t * 8 + q * 2;
                st_bf2(&y_s[r0 * EMB_LD + c0], yacc[t][0], yacc[t][1]);
                st_bf2(&y_s[r1 * EMB_LD + c0], yacc[t][2], yacc[t][3]);
            }
        }
        __syncthreads();

        // ---- outp = y @ wproj^T (96x256), k=256 in 2 chunks of 128 ----
        float pacc[16][4];
        #pragma unroll
        for (int t = 0; t < 16; t++) { pacc[t][0]=0.f; pacc[t][1]=0.f; pacc[t][2]=0.f; pacc[t][3]=0.f; }
        for (int kc = 0; kc < 2; kc++) {
            for (int idx = tid; idx < CC * 16; idx += NTH) {
                int o = idx >> 4, v = idx & 15;
                cp16(&chunk[o * PJ_LD + v * 8], &g_wprojb[o * CC + kc * 128 + v * 8]);
            }
            __syncthreads();
            #pragma unroll
            for (int kt = 0; kt < 8; kt++) {
                uint32_t a0, a1, a2, a3;
                ldsm4(a0, a1, a2, a3, aY + (kc * 128 + kt * 16) * 2);
                #pragma unroll
                for (int p = 0; p < 8; p++) {
                    uint32_t b0, b1, b2, b3;
                    ldsm4(b0, b1, b2, b3, bPjP + (p * 16 * PJ_LD + kt * 16) * 2);
                    mma16816(pacc[2*p],   a0, a1, a2, a3, b0, b1);
                    mma16816(pacc[2*p+1], a0, a1, a2, a3, b2, b3);
                }
            }
            __syncthreads();
        }

        // ---- epilogue: 2 passes, all warps active, [96][129] fp32 transpose buffer ----
        for (int p = 0; p < 2; p++) {
            int tb = p * 8;
            int r0 = rw * 16 + g, r1 = r0 + 8;
            #pragma unroll
            for (int tl = 0; tl < 8; tl++) {
                int cc = cw * 64 + tl * 8 + q * 2;
                out_s[r0 * 129 + cc]     = pacc[tb + tl][0];
                out_s[r0 * 129 + cc + 1] = pacc[tb + tl][1];
                out_s[r1 * 129 + cc]     = pacc[tb + tl][2];
                out_s[r1 * 129 + cc + 1] = pacc[tb + tl][3];
            }
            __syncthreads();
            if (evalid) {
                const float* os = out_s + nl * 129;
                #pragma unroll
                for (int it = 0; it < 32; it++) {
                    int ol = olb + it * 4;
                    int o = ol + (ol & 64) + p * 64;
                    size_t gi = ebase + (size_t)o * (HH * HH);
                    out[gi] = x[gi] + os[ol];
                }
            }
            __syncthreads();
        }
    }
}

// ---------------- launch ----------------
extern "C" void kernel_launch(void* const* d_in, const int* in_sizes, int n_in,
                              void* d_out, int out_size) {
    const float* x     = (const float*)d_in[0];
    const float* wt    = (const float*)d_in[1];
    const float* wp    = (const float*)d_in[2];
    const float* wproj = (const float*)d_in[3];
    float* out = (float*)d_out;

    cudaFuncSetAttribute(embed_kernel, cudaFuncAttributeMaxDynamicSharedMemorySize, EMBED_SMEM);
    cudaFuncSetAttribute(attn_kernel,  cudaFuncAttributeMaxDynamicSharedMemorySize, ATTN_SMEM);

    embed_kernel<<<NWIN, NTH, EMBED_SMEM>>>(x, wt, wp, wproj);
    attn_kernel<<<NWIN, NTH, ATTN_SMEM>>>(x, out);
}

// round 15
// speedup vs baseline: 1.3596x; 1.0665x over previous
#include <cuda_runtime.h>
#include <cuda_bf16.h>
#include <cstdint>

// Problem constants
#define NWIN 400
#define NTOK 324
#define NPAD 336
#define CE   128
#define CC   256
#define HH   180
#define WSZ  18

// embed (unchanged R14)
#define EBR   48
#define NBLK_E 7
#define NTH   384
#define EMB_LD 264  // words 132, mod32=4

// attn v3: per-block CTAs, 2 CTAs/SM
#define NTH_A 192
#define BLKR2 48
#define SCH   112   // S phi chunk rows
#define AVK   48    // AV k-chunk
#define TH_LD 136   // words 68,  mod32=4
#define P_LD  344   // words 172, mod32=12
#define AV_LD 56    // words 28,  mod32=28
#define PJ_LD 72    // words 36,  mod32=4

// single staging zone (elems): max(S 112*136=15232, AV 256*56=14336,
// proj 256*72=18432, epilogue fp32 48*129 = 12384 elems-as-2B*2) = 18432
#define ZONE_ELS 18432
#define OFF_TH   0
#define OFF_P    (BLKR2 * TH_LD)                 // 6528
#define OFF_Y    (OFF_P + BLKR2 * P_LD)          // 23040
#define OFF_ZONE (OFF_Y + BLKR2 * EMB_LD)        // 35712
#define OFF_END  (OFF_ZONE + ZONE_ELS)           // 54144
#define ATTN_SMEM (OFF_END * 2 + BLKR2 * 2 * 4 * 2)  // 109056 B

// ---------------- global scratch ----------------
__device__ __nv_bfloat16 g_embT [NWIN * NPAD * CC];  // [w][n][e]: e<128 theta, e>=128 phi
__device__ __nv_bfloat16 g_xw   [NWIN * CC * NPAD];  // [w][c][m]
__device__ __nv_bfloat16 g_wprojb[CC * CC];          // [o][c] (written by embed block 0)

// ---------------- helpers ----------------
__device__ __forceinline__ uint32_t s2u(const __nv_bfloat16* p) {
    return (uint32_t)__cvta_generic_to_shared(p);
}
__device__ __forceinline__ void ldsm4(uint32_t& r0, uint32_t& r1, uint32_t& r2, uint32_t& r3,
                                      uint32_t a) {
    asm volatile("ldmatrix.sync.aligned.m8n8.x4.shared.b16 {%0,%1,%2,%3}, [%4];"
        : "=r"(r0), "=r"(r1), "=r"(r2), "=r"(r3) : "r"(a));
}
__device__ __forceinline__ void ldsm2(uint32_t& r0, uint32_t& r1, uint32_t a) {
    asm volatile("ldmatrix.sync.aligned.m8n8.x2.shared.b16 {%0,%1}, [%2];"
        : "=r"(r0), "=r"(r1) : "r"(a));
}
__device__ __forceinline__ void mma16816(float* c, uint32_t a0, uint32_t a1,
                                         uint32_t a2, uint32_t a3,
                                         uint32_t b0, uint32_t b1) {
    asm volatile(
        "mma.sync.aligned.m16n8k16.row.col.f32.bf16.bf16.f32 "
        "{%0,%1,%2,%3},{%4,%5,%6,%7},{%8,%9},{%0,%1,%2,%3};\n"
        : "+f"(c[0]), "+f"(c[1]), "+f"(c[2]), "+f"(c[3])
        : "r"(a0), "r"(a1), "r"(a2), "r"(a3), "r"(b0), "r"(b1));
}
__device__ __forceinline__ void st_bf2(__nv_bfloat16* p, float lo, float hi) {
    *reinterpret_cast<__nv_bfloat162*>(p) = __floats2bfloat162_rn(lo, hi);
}
__device__ __forceinline__ void cp16(__nv_bfloat16* dst, const __nv_bfloat16* src) {
    *reinterpret_cast<uint4*>(dst) = *reinterpret_cast<const uint4*>(src);
}
__device__ __forceinline__ void cpasync16(__nv_bfloat16* smem_dst, const __nv_bfloat16* gsrc) {
    uint32_t s = (uint32_t)__cvta_generic_to_shared(smem_dst);
    asm volatile("cp.async.cg.shared.global [%0], [%1], 16;\n" :: "r"(s), "l"(gsrc));
}
#define CP_COMMIT() asm volatile("cp.async.commit_group;\n" ::: "memory")
#define CP_WAIT0()  asm volatile("cp.async.wait_group 0;\n" ::: "memory")

// ---------------- kernel 1: window partition + embed GEMM (unchanged R14) ----
#define EMBED_SMEM ((CC * EMB_LD + 2 * EBR * EMB_LD) * 2)

__global__ __launch_bounds__(NTH, 1) void embed_kernel(const float* __restrict__ x,
                                                       const float* __restrict__ wt,
                                                       const float* __restrict__ wp,
                                                       const float* __restrict__ wproj) {
    extern __shared__ char smem_raw[];
    __nv_bfloat16* wcomb_s = reinterpret_cast<__nv_bfloat16*>(smem_raw);
    __nv_bfloat16* xb0 = wcomb_s + CC * EMB_LD;
    __nv_bfloat16* xb1 = xb0 + EBR * EMB_LD;

    int w = blockIdx.x;
    int b = w / 100, rem = w % 100, wh = rem / 10, ww = rem % 10;
    int h0 = wh * WSZ, w0 = ww * WSZ;
    const float* xb = x + (size_t)b * CC * HH * HH;
    int tid = threadIdx.x;
    int warp = tid >> 5, lane = tid & 31;
    int rw = warp >> 2, cw = warp & 3;
    int g = lane >> 2, q = lane & 3;
    int lA = lane & 15, kA = (lane >> 4) << 3;
    int lB8 = lane & 7, sel = (lane >> 3) & 1, nh = lane >> 4;

    if (blockIdx.x == 0) {
        for (int idx = tid; idx < CC * CC / 4; idx += NTH) {
            float4 f = *reinterpret_cast<const float4*>(&wproj[idx * 4]);
            __nv_bfloat162 lo = __floats2bfloat162_rn(f.x, f.y);
            __nv_bfloat162 hi = __floats2bfloat162_rn(f.z, f.w);
            uint2 v; v.x = *reinterpret_cast<uint32_t*>(&lo); v.y = *reinterpret_cast<uint32_t*>(&hi);
            *reinterpret_cast<uint2*>(&g_wprojb[idx * 4]) = v;
        }
    }

    for (int idx = tid; idx < CC * 64; idx += NTH) {
        int e = idx >> 6, v = idx & 63;
        const float* src = (e < CE) ? &wt[e * CC + v * 4] : &wp[(e - CE) * CC + v * 4];
        float4 f = *reinterpret_cast<const float4*>(src);
        __nv_bfloat162 lo = __floats2bfloat162_rn(f.x, f.y);
        __nv_bfloat162 hi = __floats2bfloat162_rn(f.z, f.w);
        uint2 o; o.x = *reinterpret_cast<uint32_t*>(&lo); o.y = *reinterpret_cast<uint32_t*>(&hi);
        *reinterpret_cast<uint2*>(&wcomb_s[e * EMB_LD + v * 4]) = o;
    }

    __nv_bfloat16* xwg  = g_xw   + (size_t)w * CC * NPAD;
    __nv_bfloat16* embT = g_embT + (size_t)w * NPAD * CC;

    #pragma unroll
    for (int it = 0; it < 32; it++) {
        int idx = tid + it * NTH;
        int nn = idx % EBR, c = idx / EBR;
        int m = nn;
        float v = (m < NTOK) ? xb[((size_t)c * HH + h0 + m / WSZ) * HH + w0 + m % WSZ] : 0.f;
        __nv_bfloat16 bv = __float2bfloat16(v);
        xb0[nn * EMB_LD + c] = bv;
        xwg[c * NPAD + m] = bv;
    }
    __syncthreads();

    uint32_t aAdr[2] = { s2u(&xb0[(rw * 16 + lA) * EMB_LD + kA]),
                         s2u(&xb1[(rw * 16 + lA) * EMB_LD + kA]) };
    uint32_t bAdrP = s2u(&wcomb_s[(cw * 64 + nh * 8 + lB8) * EMB_LD + sel * 8]);

    for (int blk = 0; blk < NBLK_E; blk++) {
        float vreg[32];
        if (blk + 1 < NBLK_E) {
            #pragma unroll
            for (int it = 0; it < 32; it++) {
                int idx = tid + it * NTH;
                int nn = idx % EBR, c = idx / EBR;
                int m = (blk + 1) * EBR + nn;
                vreg[it] = (m < NTOK) ? xb[((size_t)c * HH + h0 + m / WSZ) * HH + w0 + m % WSZ] : 0.f;
            }
        }

        float acc[8][4];
        #pragma unroll
        for (int t = 0; t < 8; t++) { acc[t][0]=0.f; acc[t][1]=0.f; acc[t][2]=0.f; acc[t][3]=0.f; }
        uint32_t aA = aAdr[blk & 1];
        #pragma unroll
        for (int kt = 0; kt < 16; kt++) {
            uint32_t a0, a1, a2, a3;
            ldsm4(a0, a1, a2, a3, aA + kt * 32);
            #pragma unroll
            for (int p = 0; p < 4; p++) {
                uint32_t b0, b1, b2, b3;
                ldsm4(b0, b1, b2, b3, bAdrP + (p * 16 * EMB_LD + kt * 16) * 2);
                mma16816(acc[2*p],   a0, a1, a2, a3, b0, b1);
                mma16816(acc[2*p+1], a0, a1, a2, a3, b2, b3);
            }
        }
        {
            int r0 = blk * EBR + rw * 16 + g, r1 = r0 + 8;
            #pragma unroll
            for (int t = 0; t < 8; t++) {
                int e0 = cw * 64 + t * 8 + q * 2;
                st_bf2(&embT[r0 * CC + e0], acc[t][0], acc[t][1]);
                st_bf2(&embT[r1 * CC + e0], acc[t][2], acc[t][3]);
            }
        }
        if (blk + 1 < NBLK_E) {
            __nv_bfloat16* dst = (blk & 1) ? xb0 : xb1;
            #pragma unroll
            for (int it = 0; it < 32; it++) {
                int idx = tid + it * NTH;
                int nn = idx % EBR, c = idx / EBR;
                int m = (blk + 1) * EBR + nn;
                __nv_bfloat16 bv = __float2bfloat16(vreg[it]);
                dst[nn * EMB_LD + c] = bv;
                xwg[c * NPAD + m] = bv;
            }
        }
        __syncthreads();
    }
}

// ---------------- kernel 2: attn v3 — one 48-row block per 192-thread CTA, 2 CTAs/SM ----
__global__ __launch_bounds__(NTH_A, 2) void attn_kernel(const float* __restrict__ x,
                                                        float* __restrict__ out) {
    extern __shared__ char smem_raw[];
    __nv_bfloat16* sm    = reinterpret_cast<__nv_bfloat16*>(smem_raw);
    __nv_bfloat16* th_s  = sm + OFF_TH;     // [48][TH_LD]
    __nv_bfloat16* P_s   = sm + OFF_P;      // [48][P_LD]
    __nv_bfloat16* y_s   = sm + OFF_Y;      // [48][EMB_LD]
    __nv_bfloat16* zone  = sm + OFF_ZONE;   // staging zone (S/AV/proj/epilogue)
    float* stats_max = reinterpret_cast<float*>(sm + OFF_END);
    float* stats_sum = stats_max + BLKR2 * 2;
    float* out_s = reinterpret_cast<float*>(zone);   // fp32 [48][129]

    int bid = blockIdx.x;
    int w = bid / NBLK_E, blk = bid - w * NBLK_E;
    int b = w / 100, rem = w % 100, wh = rem / 10, ww = rem % 10;
    int h0 = wh * WSZ, w0 = ww * WSZ;
    int tid = threadIdx.x;
    int warp = tid >> 5, lane = tid & 31;
    int rw = warp >> 1, cw = warp & 1;   // 3 x 2
    int g = lane >> 2, q = lane & 3;
    int lA = lane & 15, kA = (lane >> 4) << 3;
    int lB8 = lane & 7, sel = (lane >> 3) & 1, nh = lane >> 4;

    const __nv_bfloat16* embT = g_embT + (size_t)w * NPAD * CC;
    const __nv_bfloat16* xwg  = g_xw   + (size_t)w * CC * NPAD;

    const float scale = 0.08838834764831845f;  // 1/sqrt(128)

    // ldmatrix bases
    uint32_t aTh = s2u(&th_s[(rw * 16 + lA) * TH_LD + kA]);
    uint32_t aP  = s2u(&P_s[(rw * 16 + lA) * P_LD + kA]);
    uint32_t aY  = s2u(&y_s[(rw * 16 + lA) * EMB_LD + kA]);
    uint32_t bPhi = s2u(&zone[(cw * 56 + nh * 8 + lB8) * TH_LD + sel * 8]);
    uint32_t bPhiS = s2u(&zone[(cw * 56 + 48 + lB8) * TH_LD + sel * 8]);
    uint32_t bAv  = s2u(&zone[(cw * 128 + nh * 8 + lB8) * AV_LD + sel * 8]);
    uint32_t bPj  = s2u(&zone[(cw * 128 + nh * 8 + lB8) * PJ_LD + sel * 8]);

    // strength-reduced constants (NTH_A=192 = 32*6 = 48*4)
    int v6 = tid % 6, c6 = tid / 6;          // AV staging: 8 iters, c += 32
    int nl = tid % 48, olb = tid / 48;       // epilogue: 32 iters, ol += 4

    // epilogue per-thread precompute
    int ng = blk * BLKR2 + nl;
    bool evalid = (ng < NTOK);
    size_t ebase = 0;
    if (evalid) {
        int i = ng / WSZ, j = ng - i * WSZ;
        ebase = ((size_t)b * CC * HH + h0 + i) * HH + w0 + j;
    }

    // ---- stage S chunk 0 (async) + theta rows (sync copies) ----
    for (int idx = tid; idx < SCH * 16; idx += NTH_A) {
        int mm = idx >> 4, v = idx & 15;
        cpasync16(&zone[mm * TH_LD + v * 8], &embT[mm * CC + CE + v * 8]);
    }
    CP_COMMIT();
    for (int idx = tid; idx < BLKR2 * 16; idx += NTH_A) {
        int r = idx >> 4, v = idx & 15;
        cp16(&th_s[r * TH_LD + v * 8], &embT[(blk * BLKR2 + r) * CC + v * 8]);
    }

    // ---- S = theta_blk @ phi^T (48x336), k=128, 3 single-buffered chunks ----
    float sacc[21][4];
    #pragma unroll
    for (int t = 0; t < 21; t++) { sacc[t][0]=0.f; sacc[t][1]=0.f; sacc[t][2]=0.f; sacc[t][3]=0.f; }
    for (int mc = 0; mc < 3; mc++) {
        if (mc > 0) {
            __syncthreads();   // previous chunk fully consumed
            for (int idx = tid; idx < SCH * 16; idx += NTH_A) {
                int mm = idx >> 4, v = idx & 15;
                cpasync16(&zone[mm * TH_LD + v * 8], &embT[(mc * SCH + mm) * CC + CE + v * 8]);
            }
            CP_COMMIT();
        }
        CP_WAIT0();
        __syncthreads();
        #pragma unroll
        for (int kt = 0; kt < 8; kt++) {
            uint32_t a0, a1, a2, a3;
            ldsm4(a0, a1, a2, a3, aTh + kt * 32);
            #pragma unroll
            for (int p = 0; p < 3; p++) {
                uint32_t b0, b1, b2, b3;
                ldsm4(b0, b1, b2, b3, bPhi + (p * 16 * TH_LD + kt * 16) * 2);
                mma16816(sacc[mc * 7 + 2*p],   a0, a1, a2, a3, b0, b1);
                mma16816(sacc[mc * 7 + 2*p+1], a0, a1, a2, a3, b2, b3);
            }
            {
                uint32_t b0, b1;
                ldsm2(b0, b1, bPhiS + kt * 32);
                mma16816(sacc[mc * 7 + 6], a0, a1, a2, a3, b0, b1);
            }
        }
    }
    // ---- scale + column mask ----
    #pragma unroll
    for (int mc = 0; mc < 3; mc++) {
        #pragma unroll
        for (int t = 0; t < 7; t++) {
            int c0 = mc * SCH + cw * 56 + t * 8 + q * 2;
            float* sv = sacc[mc * 7 + t];
            #pragma unroll
            for (int i = 0; i < 4; i++) {
                float v = sv[i] * scale;
                int col = c0 + (i & 1);
                if (col >= NTOK) v = -1e30f;
                sv[i] = v;
            }
        }
    }
    // ---- row max ----
    float m0 = -1e30f, m1 = -1e30f;
    #pragma unroll
    for (int t = 0; t < 21; t++) {
        m0 = fmaxf(m0, fmaxf(sacc[t][0], sacc[t][1]));
        m1 = fmaxf(m1, fmaxf(sacc[t][2], sacc[t][3]));
    }
    m0 = fmaxf(m0, __shfl_xor_sync(0xffffffffu, m0, 1));
    m0 = fmaxf(m0, __shfl_xor_sync(0xffffffffu, m0, 2));
    m1 = fmaxf(m1, __shfl_xor_sync(0xffffffffu, m1, 1));
    m1 = fmaxf(m1, __shfl_xor_sync(0xffffffffu, m1, 2));
    int row0 = rw * 16 + g, row1 = row0 + 8;
    if (q == 0) { stats_max[row0 * 2 + cw] = m0; stats_max[row1 * 2 + cw] = m1; }
    __syncthreads();
    float rmax0 = fmaxf(stats_max[row0 * 2], stats_max[row0 * 2 + 1]);
    float rmax1 = fmaxf(stats_max[row1 * 2], stats_max[row1 * 2 + 1]);
    // ---- exp + row sums ----
    float s0 = 0.f, s1 = 0.f;
    #pragma unroll
    for (int t = 0; t < 21; t++) {
        sacc[t][0] = __expf(sacc[t][0] - rmax0);
        sacc[t][1] = __expf(sacc[t][1] - rmax0);
        sacc[t][2] = __expf(sacc[t][2] - rmax1);
        sacc[t][3] = __expf(sacc[t][3] - rmax1);
        s0 += sacc[t][0] + sacc[t][1];
        s1 += sacc[t][2] + sacc[t][3];
    }
    s0 += __shfl_xor_sync(0xffffffffu, s0, 1);
    s0 += __shfl_xor_sync(0xffffffffu, s0, 2);
    s1 += __shfl_xor_sync(0xffffffffu, s1, 1);
    s1 += __shfl_xor_sync(0xffffffffu, s1, 2);
    if (q == 0) { stats_sum[row0 * 2 + cw] = s0; stats_sum[row1 * 2 + cw] = s1; }
    __syncthreads();
    float inv0 = 1.f / (stats_sum[row0 * 2] + stats_sum[row0 * 2 + 1]);
    float inv1 = 1.f / (stats_sum[row1 * 2] + stats_sum[row1 * 2 + 1]);
    // ---- write normalized P ----
    #pragma unroll
    for (int mc = 0; mc < 3; mc++) {
        #pragma unroll
        for (int t = 0; t < 7; t++) {
            int c0 = mc * SCH + cw * 56 + t * 8 + q * 2;
            float* sv = sacc[mc * 7 + t];
            st_bf2(&P_s[row0 * P_LD + c0], sv[0] * inv0, sv[1] * inv0);
            st_bf2(&P_s[row1 * P_LD + c0], sv[2] * inv1, sv[3] * inv1);
        }
    }

    // ---- y = P @ xw^T (48x256), k=336 in 7 single-buffered chunks of 48 ----
    float yacc[16][4];
    #pragma unroll
    for (int t = 0; t < 16; t++) { yacc[t][0]=0.f; yacc[t][1]=0.f; yacc[t][2]=0.f; yacc[t][3]=0.f; }
    for (int mc = 0; mc < 7; mc++) {
        if (mc > 0) __syncthreads();        // zone consumed (for mc=0 the stats syncs cover it)
        {
            const __nv_bfloat16* src = xwg + c6 * NPAD + mc * AVK + v6 * 8;
            __nv_bfloat16* dst = zone + c6 * AV_LD + v6 * 8;
            #pragma unroll
            for (int it = 0; it < 8; it++)
                cpasync16(dst + it * 32 * AV_LD, src + it * 32 * NPAD);
        }
        CP_COMMIT();
        CP_WAIT0();
        __syncthreads();   // zone ready; also publishes P_s on mc=0
        #pragma unroll
        for (int kt = 0; kt < 3; kt++) {
            uint32_t a0, a1, a2, a3;
            ldsm4(a0, a1, a2, a3, aP + (mc * AVK + kt * 16) * 2);
            #pragma unroll
            for (int p = 0; p < 8; p++) {
                uint32_t b0, b1, b2, b3;
                ldsm4(b0, b1, b2, b3, bAv + (p * 16 * AV_LD + kt * 16) * 2);
                mma16816(yacc[2*p],   a0, a1, a2, a3, b0, b1);
                mma16816(yacc[2*p+1], a0, a1, a2, a3, b2, b3);
            }
        }
    }
    // ---- stage y (bf16) ----
    {
        int r0 = rw * 16 + g, r1 = r0 + 8;
        #pragma unroll
        for (int t = 0; t < 16; t++) {
            int c0 = cw * 128 + t * 8 + q * 2;
            st_bf2(&y_s[r0 * EMB_LD + c0], yacc[t][0], yacc[t][1]);
            st_bf2(&y_s[r1 * EMB_LD + c0], yacc[t][2], yacc[t][3]);
        }
    }

    // ---- outp = y @ wproj^T (48x256), k=256 in 4 single-buffered stages of 64 ----
    float pacc[16][4];
    #pragma unroll
    for (int t = 0; t < 16; t++) { pacc[t][0]=0.f; pacc[t][1]=0.f; pacc[t][2]=0.f; pacc[t][3]=0.f; }
    for (int kc = 0; kc < 4; kc++) {
        __syncthreads();   // zone consumed (kc=0: also publishes y_s, ends last AV reads)
        for (int idx = tid; idx < CC * 8; idx += NTH_A) {
            int o = idx >> 3, v = idx & 7;
            cpasync16(&zone[o * PJ_LD + v * 8], &g_wprojb[o * CC + kc * 64 + v * 8]);
        }
        CP_COMMIT();
        CP_WAIT0();
        __syncthreads();
        #pragma unroll
        for (int kt = 0; kt < 4; kt++) {
            uint32_t a0, a1, a2, a3;
            ldsm4(a0, a1, a2, a3, aY + (kc * 64 + kt * 16) * 2);
            #pragma unroll
            for (int p = 0; p < 8; p++) {
                uint32_t b0, b1, b2, b3;
                ldsm4(b0, b1, b2, b3, bPj + (p * 16 * PJ_LD + kt * 16) * 2);
                mma16816(pacc[2*p],   a0, a1, a2, a3, b0, b1);
                mma16816(pacc[2*p+1], a0, a1, a2, a3, b2, b3);
            }
        }
    }

    // ---- epilogue: 2 passes, [48][129] fp32 transpose buffer in zone ----
    for (int p = 0; p < 2; p++) {
        __syncthreads();   // zone free (p=0: last proj reads done)
        int tb = p * 8;
        int r0 = rw * 16 + g, r1 = r0 + 8;
        #pragma unroll
        for (int tl = 0; tl < 8; tl++) {
            int cc = cw * 64 + tl * 8 + q * 2;
            out_s[r0 * 129 + cc]     = pacc[tb + tl][0];
            out_s[r0 * 129 + cc + 1] = pacc[tb + tl][1];
            out_s[r1 * 129 + cc]     = pacc[tb + tl][2];
            out_s[r1 * 129 + cc + 1] = pacc[tb + tl][3];
        }
        __syncthreads();
        if (evalid) {
            const float* os = out_s + nl * 129;
            #pragma unroll
            for (int it = 0; it < 32; it++) {
                int ol = olb + it * 4;
                int o = ol + (ol & 64) + p * 64;
                size_t gi = ebase + (size_t)o * (HH * HH);
                out[gi] = x[gi] + os[ol];
            }
        }
    }
}

// ---------------- launch ----------------
extern "C" void kernel_launch(void* const* d_in, const int* in_sizes, int n_in,
                              void* d_out, int out_size) {
    const float* x     = (const float*)d_in[0];
    const float* wt    = (const float*)d_in[1];
    const float* wp    = (const float*)d_in[2];
    const float* wproj = (const float*)d_in[3];
    float* out = (float*)d_out;

    cudaFuncSetAttribute(embed_kernel, cudaFuncAttributeMaxDynamicSharedMemorySize, EMBED_SMEM);
    cudaFuncSetAttribute(attn_kernel,  cudaFuncAttributeMaxDynamicSharedMemorySize, ATTN_SMEM);

    embed_kernel<<<NWIN, NTH, EMBED_SMEM>>>(x, wt, wp, wproj);
    attn_kernel<<<NWIN * NBLK_E, NTH_A, ATTN_SMEM>>>(x, out);
}

// round 16
// speedup vs baseline: 1.4534x; 1.0690x over previous
#include <cuda_runtime.h>
#include <cuda_bf16.h>
#include <cstdint>

// Problem constants
#define NWIN 400
#define NTOK 324
#define NPAD 336
#define CE   128
#define CC   256
#define HH   180
#define WSZ  18

// embed (unchanged)
#define EBR   48
#define NBLK_E 7
#define NTH   384
#define EMB_LD 264  // words 132, mod32=4

// attn v4: per-block CTAs, 2 CTAs/SM, double-buffered zone, register-resident y
#define NTH_A 192
#define BLKR2 48
#define SCH   112   // S phi chunk rows
#define AVK   48    // AV k-chunk
#define TH_LD 136   // words 68,  mod32=4
#define P_LD  344   // words 172, mod32=12
#define AV_LD 56    // words 28,  mod32=28
#define PJ_LD 72    // words 36,  mod32=4

// zone: 2 ping-pong halves; each holds max(S 112*136=15232, AV 256*56=14336,
// proj 128*72=9216) elems; epilogue fp32 [48][129]=24768B fits one half (30464B)
#define ZONE_HALF 15232
#define OFF_P    (BLKR2 * TH_LD)                  // 6528
#define OFF_ZONE (OFF_P + BLKR2 * P_LD)           // 23040
#define OFF_END  (OFF_ZONE + 2 * ZONE_HALF)       // 53504
#define ATTN_SMEM (OFF_END * 2 + BLKR2 * 2 * 4 * 2)  // 107776 B

// ---------------- global scratch ----------------
__device__ __nv_bfloat16 g_embT [NWIN * NPAD * CC];  // [w][n][e]: e<128 theta, e>=128 phi
__device__ __nv_bfloat16 g_xw   [NWIN * CC * NPAD];  // [w][c][m]
__device__ __nv_bfloat16 g_wprojb[CC * CC];          // [o][c]

// ---------------- helpers ----------------
__device__ __forceinline__ uint32_t s2u(const __nv_bfloat16* p) {
    return (uint32_t)__cvta_generic_to_shared(p);
}
__device__ __forceinline__ void ldsm4(uint32_t& r0, uint32_t& r1, uint32_t& r2, uint32_t& r3,
                                      uint32_t a) {
    asm volatile("ldmatrix.sync.aligned.m8n8.x4.shared.b16 {%0,%1,%2,%3}, [%4];"
        : "=r"(r0), "=r"(r1), "=r"(r2), "=r"(r3) : "r"(a));
}
__device__ __forceinline__ void ldsm2(uint32_t& r0, uint32_t& r1, uint32_t a) {
    asm volatile("ldmatrix.sync.aligned.m8n8.x2.shared.b16 {%0,%1}, [%2];"
        : "=r"(r0), "=r"(r1) : "r"(a));
}
__device__ __forceinline__ void mma16816(float* c, uint32_t a0, uint32_t a1,
                                         uint32_t a2, uint32_t a3,
                                         uint32_t b0, uint32_t b1) {
    asm volatile(
        "mma.sync.aligned.m16n8k16.row.col.f32.bf16.bf16.f32 "
        "{%0,%1,%2,%3},{%4,%5,%6,%7},{%8,%9},{%0,%1,%2,%3};\n"
        : "+f"(c[0]), "+f"(c[1]), "+f"(c[2]), "+f"(c[3])
        : "r"(a0), "r"(a1), "r"(a2), "r"(a3), "r"(b0), "r"(b1));
}
__device__ __forceinline__ void st_bf2(__nv_bfloat16* p, float lo, float hi) {
    *reinterpret_cast<__nv_bfloat162*>(p) = __floats2bfloat162_rn(lo, hi);
}
__device__ __forceinline__ uint32_t pk2(float lo, float hi) {
    __nv_bfloat162 v = __floats2bfloat162_rn(lo, hi);
    return *reinterpret_cast<uint32_t*>(&v);
}
__device__ __forceinline__ void cp16(__nv_bfloat16* dst, const __nv_bfloat16* src) {
    *reinterpret_cast<uint4*>(dst) = *reinterpret_cast<const uint4*>(src);
}
__device__ __forceinline__ void cpasync16(__nv_bfloat16* smem_dst, const __nv_bfloat16* gsrc) {
    uint32_t s = (uint32_t)__cvta_generic_to_shared(smem_dst);
    asm volatile("cp.async.cg.shared.global [%0], [%1], 16;\n" :: "r"(s), "l"(gsrc));
}
#define CP_COMMIT() asm volatile("cp.async.commit_group;\n" ::: "memory")
#define CP_WAIT1()  asm volatile("cp.async.wait_group 1;\n" ::: "memory")
#define CP_WAIT0()  asm volatile("cp.async.wait_group 0;\n" ::: "memory")

// ---------------- kernel 1: window partition + embed GEMM (unchanged) ----
#define EMBED_SMEM ((CC * EMB_LD + 2 * EBR * EMB_LD) * 2)

__global__ __launch_bounds__(NTH, 1) void embed_kernel(const float* __restrict__ x,
                                                       const float* __restrict__ wt,
                                                       const float* __restrict__ wp,
                                                       const float* __restrict__ wproj) {
    extern __shared__ char smem_raw[];
    __nv_bfloat16* wcomb_s = reinterpret_cast<__nv_bfloat16*>(smem_raw);
    __nv_bfloat16* xb0 = wcomb_s + CC * EMB_LD;
    __nv_bfloat16* xb1 = xb0 + EBR * EMB_LD;

    int w = blockIdx.x;
    int b = w / 100, rem = w % 100, wh = rem / 10, ww = rem % 10;
    int h0 = wh * WSZ, w0 = ww * WSZ;
    const float* xb = x + (size_t)b * CC * HH * HH;
    int tid = threadIdx.x;
    int warp = tid >> 5, lane = tid & 31;
    int rw = warp >> 2, cw = warp & 3;
    int g = lane >> 2, q = lane & 3;
    int lA = lane & 15, kA = (lane >> 4) << 3;
    int lB8 = lane & 7, sel = (lane >> 3) & 1, nh = lane >> 4;

    if (blockIdx.x == 0) {
        for (int idx = tid; idx < CC * CC / 4; idx += NTH) {
            float4 f = *reinterpret_cast<const float4*>(&wproj[idx * 4]);
            __nv_bfloat162 lo = __floats2bfloat162_rn(f.x, f.y);
            __nv_bfloat162 hi = __floats2bfloat162_rn(f.z, f.w);
            uint2 v; v.x = *reinterpret_cast<uint32_t*>(&lo); v.y = *reinterpret_cast<uint32_t*>(&hi);
            *reinterpret_cast<uint2*>(&g_wprojb[idx * 4]) = v;
        }
    }

    for (int idx = tid; idx < CC * 64; idx += NTH) {
        int e = idx >> 6, v = idx & 63;
        const float* src = (e < CE) ? &wt[e * CC + v * 4] : &wp[(e - CE) * CC + v * 4];
        float4 f = *reinterpret_cast<const float4*>(src);
        __nv_bfloat162 lo = __floats2bfloat162_rn(f.x, f.y);
        __nv_bfloat162 hi = __floats2bfloat162_rn(f.z, f.w);
        uint2 o; o.x = *reinterpret_cast<uint32_t*>(&lo); o.y = *reinterpret_cast<uint32_t*>(&hi);
        *reinterpret_cast<uint2*>(&wcomb_s[e * EMB_LD + v * 4]) = o;
    }

    __nv_bfloat16* xwg  = g_xw   + (size_t)w * CC * NPAD;
    __nv_bfloat16* embT = g_embT + (size_t)w * NPAD * CC;

    #pragma unroll
    for (int it = 0; it < 32; it++) {
        int idx = tid + it * NTH;
        int nn = idx % EBR, c = idx / EBR;
        int m = nn;
        float v = (m < NTOK) ? xb[((size_t)c * HH + h0 + m / WSZ) * HH + w0 + m % WSZ] : 0.f;
        __nv_bfloat16 bv = __float2bfloat16(v);
        xb0[nn * EMB_LD + c] = bv;
        xwg[c * NPAD + m] = bv;
    }
    __syncthreads();

    uint32_t aAdr[2] = { s2u(&xb0[(rw * 16 + lA) * EMB_LD + kA]),
                         s2u(&xb1[(rw * 16 + lA) * EMB_LD + kA]) };
    uint32_t bAdrP = s2u(&wcomb_s[(cw * 64 + nh * 8 + lB8) * EMB_LD + sel * 8]);

    for (int blk = 0; blk < NBLK_E; blk++) {
        float vreg[32];
        if (blk + 1 < NBLK_E) {
            #pragma unroll
            for (int it = 0; it < 32; it++) {
                int idx = tid + it * NTH;
                int nn = idx % EBR, c = idx / EBR;
                int m = (blk + 1) * EBR + nn;
                vreg[it] = (m < NTOK) ? xb[((size_t)c * HH + h0 + m / WSZ) * HH + w0 + m % WSZ] : 0.f;
            }
        }

        float acc[8][4];
        #pragma unroll
        for (int t = 0; t < 8; t++) { acc[t][0]=0.f; acc[t][1]=0.f; acc[t][2]=0.f; acc[t][3]=0.f; }
        uint32_t aA = aAdr[blk & 1];
        #pragma unroll
        for (int kt = 0; kt < 16; kt++) {
            uint32_t a0, a1, a2, a3;
            ldsm4(a0, a1, a2, a3, aA + kt * 32);
            #pragma unroll
            for (int p = 0; p < 4; p++) {
                uint32_t b0, b1, b2, b3;
                ldsm4(b0, b1, b2, b3, bAdrP + (p * 16 * EMB_LD + kt * 16) * 2);
                mma16816(acc[2*p],   a0, a1, a2, a3, b0, b1);
                mma16816(acc[2*p+1], a0, a1, a2, a3, b2, b3);
            }
        }
        {
            int r0 = blk * EBR + rw * 16 + g, r1 = r0 + 8;
            #pragma unroll
            for (int t = 0; t < 8; t++) {
                int e0 = cw * 64 + t * 8 + q * 2;
                st_bf2(&embT[r0 * CC + e0], acc[t][0], acc[t][1]);
                st_bf2(&embT[r1 * CC + e0], acc[t][2], acc[t][3]);
            }
        }
        if (blk + 1 < NBLK_E) {
            __nv_bfloat16* dst = (blk & 1) ? xb0 : xb1;
            #pragma unroll
            for (int it = 0; it < 32; it++) {
                int idx = tid + it * NTH;
                int nn = idx % EBR, c = idx / EBR;
                int m = (blk + 1) * EBR + nn;
                __nv_bfloat16 bv = __float2bfloat16(vreg[it]);
                dst[nn * EMB_LD + c] = bv;
                xwg[c * NPAD + m] = bv;
            }
        }
        __syncthreads();
    }
}

// ---------------- kernel 2: attn v4 ----------------
__global__ __launch_bounds__(NTH_A, 2) void attn_kernel(const float* __restrict__ x,
                                                        float* __restrict__ out) {
    extern __shared__ char smem_raw[];
    __nv_bfloat16* sm    = reinterpret_cast<__nv_bfloat16*>(smem_raw);
    __nv_bfloat16* th_s  = sm;                       // [48][TH_LD]
    __nv_bfloat16* P_s   = sm + OFF_P;               // [48][P_LD]
    __nv_bfloat16* zb[2] = { sm + OFF_ZONE, sm + OFF_ZONE + ZONE_HALF };
    float* stats_max = reinterpret_cast<float*>(sm + OFF_END);
    float* stats_sum = stats_max + BLKR2 * 2;
    float* out_s = reinterpret_cast<float*>(zb[1]);  // fp32 [48][129] (always zone1)

    int bid = blockIdx.x;
    int w = bid / NBLK_E, blk = bid - w * NBLK_E;
    int b = w / 100, rem = w % 100, wh = rem / 10, ww = rem % 10;
    int h0 = wh * WSZ, w0 = ww * WSZ;
    int tid = threadIdx.x;
    int warp = tid >> 5, lane = tid & 31;
    int rw = warp >> 1, cw = warp & 1;   // 3 x 2
    int g = lane >> 2, q = lane & 3;
    int lA = lane & 15, kA = (lane >> 4) << 3;
    int lB8 = lane & 7, sel = (lane >> 3) & 1, nh = lane >> 4;

    const __nv_bfloat16* embT = g_embT + (size_t)w * NPAD * CC;
    const __nv_bfloat16* xwg  = g_xw   + (size_t)w * CC * NPAD;

    const float scale = 0.08838834764831845f;  // 1/sqrt(128)

    // ldmatrix bases
    uint32_t aTh = s2u(&th_s[(rw * 16 + lA) * TH_LD + kA]);
    uint32_t aP  = s2u(&P_s[(rw * 16 + lA) * P_LD + kA]);
    uint32_t bPhiP[2] = { s2u(&zb[0][(cw * 56 + nh * 8 + lB8) * TH_LD + sel * 8]),
                          s2u(&zb[1][(cw * 56 + nh * 8 + lB8) * TH_LD + sel * 8]) };
    uint32_t bPhiS[2] = { s2u(&zb[0][(cw * 56 + 48 + lB8) * TH_LD + sel * 8]),
                          s2u(&zb[1][(cw * 56 + 48 + lB8) * TH_LD + sel * 8]) };
    uint32_t bAvP[2] = { s2u(&zb[0][(cw * 128 + nh * 8 + lB8) * AV_LD + sel * 8]),
                         s2u(&zb[1][(cw * 128 + nh * 8 + lB8) * AV_LD + sel * 8]) };
    uint32_t bPjP[2] = { s2u(&zb[0][(nh * 8 + lB8) * PJ_LD + cw * 32 + sel * 8]),
                         s2u(&zb[1][(nh * 8 + lB8) * PJ_LD + cw * 32 + sel * 8]) };

    // strength-reduced staging constants (192 = 32*6 = 48*4)
    int v6 = tid % 6, c6 = tid / 6;          // AV staging: 8 iters, c += 32
    int nl = tid % 48, ob = tid / 48;        // epilogue: 32 iters, o += 4

    // epilogue per-thread precompute
    int ng = blk * BLKR2 + nl;
    bool evalid = (ng < NTOK);
    size_t ebase = 0;
    if (evalid) {
        int i = ng / WSZ, j = ng - i * WSZ;
        ebase = ((size_t)b * CC * HH + h0 + i) * HH + w0 + j;
    }

    // ---- S phase: prefetch chunk 0 + theta stage ----
    for (int idx = tid; idx < SCH * 16; idx += NTH_A) {
        int mm = idx >> 4, v = idx & 15;
        cpasync16(&zb[0][mm * TH_LD + v * 8], &embT[mm * CC + CE + v * 8]);
    }
    CP_COMMIT();
    for (int idx = tid; idx < BLKR2 * 16; idx += NTH_A) {
        int r = idx >> 4, v = idx & 15;
        cp16(&th_s[r * TH_LD + v * 8], &embT[(blk * BLKR2 + r) * CC + v * 8]);
    }

    float sacc[21][4];
    #pragma unroll
    for (int t = 0; t < 21; t++) { sacc[t][0]=0.f; sacc[t][1]=0.f; sacc[t][2]=0.f; sacc[t][3]=0.f; }
    for (int mc = 0; mc < 3; mc++) {
        if (mc < 2) {
            for (int idx = tid; idx < SCH * 16; idx += NTH_A) {
                int mm = idx >> 4, v = idx & 15;
                cpasync16(&zb[(mc + 1) & 1][mm * TH_LD + v * 8],
                          &embT[((mc + 1) * SCH + mm) * CC + CE + v * 8]);
            }
            CP_COMMIT();
            CP_WAIT1();
        } else {
            CP_WAIT0();
        }
        __syncthreads();
        uint32_t bP = bPhiP[mc & 1], bS = bPhiS[mc & 1];
        #pragma unroll
        for (int kt = 0; kt < 8; kt++) {
            uint32_t a0, a1, a2, a3;
            ldsm4(a0, a1, a2, a3, aTh + kt * 32);
            #pragma unroll
            for (int p = 0; p < 3; p++) {
                uint32_t b0, b1, b2, b3;
                ldsm4(b0, b1, b2, b3, bP + (p * 16 * TH_LD + kt * 16) * 2);
                mma16816(sacc[mc * 7 + 2*p],   a0, a1, a2, a3, b0, b1);
                mma16816(sacc[mc * 7 + 2*p+1], a0, a1, a2, a3, b2, b3);
            }
            {
                uint32_t b0, b1;
                ldsm2(b0, b1, bS + kt * 32);
                mma16816(sacc[mc * 7 + 6], a0, a1, a2, a3, b0, b1);
            }
        }
        __syncthreads();
    }
    // prefetch AV chunk 0 -> zb1 (free: S c1 consumed); overlap with softmax
    {
        const __nv_bfloat16* src = xwg + c6 * NPAD + v6 * 8;
        __nv_bfloat16* dst = zb[1] + c6 * AV_LD + v6 * 8;
        #pragma unroll
        for (int it = 0; it < 8; it++)
            cpasync16(dst + it * 32 * AV_LD, src + it * 32 * NPAD);
    }
    CP_COMMIT();

    // ---- softmax ----
    #pragma unroll
    for (int mc = 0; mc < 3; mc++) {
        #pragma unroll
        for (int t = 0; t < 7; t++) {
            int c0 = mc * SCH + cw * 56 + t * 8 + q * 2;
            float* sv = sacc[mc * 7 + t];
            #pragma unroll
            for (int i = 0; i < 4; i++) {
                float v = sv[i] * scale;
                int col = c0 + (i & 1);
                if (col >= NTOK) v = -1e30f;
                sv[i] = v;
            }
        }
    }
    float m0 = -1e30f, m1 = -1e30f;
    #pragma unroll
    for (int t = 0; t < 21; t++) {
        m0 = fmaxf(m0, fmaxf(sacc[t][0], sacc[t][1]));
        m1 = fmaxf(m1, fmaxf(sacc[t][2], sacc[t][3]));
    }
    m0 = fmaxf(m0, __shfl_xor_sync(0xffffffffu, m0, 1));
    m0 = fmaxf(m0, __shfl_xor_sync(0xffffffffu, m0, 2));
    m1 = fmaxf(m1, __shfl_xor_sync(0xffffffffu, m1, 1));
    m1 = fmaxf(m1, __shfl_xor_sync(0xffffffffu, m1, 2));
    int row0 = rw * 16 + g, row1 = row0 + 8;
    if (q == 0) { stats_max[row0 * 2 + cw] = m0; stats_max[row1 * 2 + cw] = m1; }
    __syncthreads();
    float rmax0 = fmaxf(stats_max[row0 * 2], stats_max[row0 * 2 + 1]);
    float rmax1 = fmaxf(stats_max[row1 * 2], stats_max[row1 * 2 + 1]);
    float s0 = 0.f, s1 = 0.f;
    #pragma unroll
    for (int t = 0; t < 21; t++) {
        sacc[t][0] = __expf(sacc[t][0] - rmax0);
        sacc[t][1] = __expf(sacc[t][1] - rmax0);
        sacc[t][2] = __expf(sacc[t][2] - rmax1);
        sacc[t][3] = __expf(sacc[t][3] - rmax1);
        s0 += sacc[t][0] + sacc[t][1];
        s1 += sacc[t][2] + sacc[t][3];
    }
    s0 += __shfl_xor_sync(0xffffffffu, s0, 1);
    s0 += __shfl_xor_sync(0xffffffffu, s0, 2);
    s1 += __shfl_xor_sync(0xffffffffu, s1, 1);
    s1 += __shfl_xor_sync(0xffffffffu, s1, 2);
    if (q == 0) { stats_sum[row0 * 2 + cw] = s0; stats_sum[row1 * 2 + cw] = s1; }
    __syncthreads();
    float inv0 = 1.f / (stats_sum[row0 * 2] + stats_sum[row0 * 2 + 1]);
    float inv1 = 1.f / (stats_sum[row1 * 2] + stats_sum[row1 * 2 + 1]);
    #pragma unroll
    for (int mc = 0; mc < 3; mc++) {
        #pragma unroll
        for (int t = 0; t < 7; t++) {
            int c0 = mc * SCH + cw * 56 + t * 8 + q * 2;
            float* sv = sacc[mc * 7 + t];
            st_bf2(&P_s[row0 * P_LD + c0], sv[0] * inv0, sv[1] * inv0);
            st_bf2(&P_s[row1 * P_LD + c0], sv[2] * inv1, sv[3] * inv1);
        }
    }

    // ---- AV: y = P @ xw^T (48x256), 7 double-buffered chunks; chunk mc in zb[(mc+1)&1] ----
    float yacc[16][4];
    #pragma unroll
    for (int t = 0; t < 16; t++) { yacc[t][0]=0.f; yacc[t][1]=0.f; yacc[t][2]=0.f; yacc[t][3]=0.f; }
    for (int mc = 0; mc < 7; mc++) {
        if (mc < 6) {
            const __nv_bfloat16* src = xwg + c6 * NPAD + (mc + 1) * AVK + v6 * 8;
            __nv_bfloat16* dst = zb[mc & 1] + c6 * AV_LD + v6 * 8;
            #pragma unroll
            for (int it = 0; it < 8; it++)
                cpasync16(dst + it * 32 * AV_LD, src + it * 32 * NPAD);
            CP_COMMIT();
            CP_WAIT1();
        } else {
            CP_WAIT0();
        }
        __syncthreads();   // mc=0: also publishes P_s
        uint32_t bAv = bAvP[(mc + 1) & 1];
        #pragma unroll
        for (int kt = 0; kt < 3; kt++) {
            uint32_t a0, a1, a2, a3;
            ldsm4(a0, a1, a2, a3, aP + (mc * AVK + kt * 16) * 2);
            #pragma unroll
            for (int p = 0; p < 8; p++) {
                uint32_t b0, b1, b2, b3;
                ldsm4(b0, b1, b2, b3, bAv + (p * 16 * AV_LD + kt * 16) * 2);
                mma16816(yacc[2*p],   a0, a1, a2, a3, b0, b1);
                mma16816(yacc[2*p+1], a0, a1, a2, a3, b2, b3);
            }
        }
        __syncthreads();
    }

    // ---- pack y into proj A-fragments (C-frag == A-frag layout); k = warp's 128 channels ----
    uint32_t pY[8][4];
    #pragma unroll
    for (int t = 0; t < 8; t++) {
        pY[t][0] = pk2(yacc[2*t][0],   yacc[2*t][1]);
        pY[t][1] = pk2(yacc[2*t][2],   yacc[2*t][3]);
        pY[t][2] = pk2(yacc[2*t+1][0], yacc[2*t+1][1]);
        pY[t][3] = pk2(yacc[2*t+1][2], yacc[2*t+1][3]);
    }

    // ---- proj: out = y @ wproj^T, k split by cw (partial sums merged in epilogue) ----
    // 8 stages idx = h*4+sp: o-rows h*128..+127, c-window [sp*32, +32) per cw half,
    // staged side-by-side as [128][PJ_LD] (cw0 cols 0..31, cw1 cols 32..63)
    // prefetch stage 0 -> zb0 (free: AV c5 consumed)
    for (int idx = tid; idx < 128 * 8; idx += NTH_A) {
        int o = idx >> 3, u = idx & 7;
        int csrc = (u < 4) ? (u * 8) : (128 + (u - 4) * 8);
        cpasync16(&zb[0][o * PJ_LD + u * 8], &g_wprojb[o * CC + csrc]);
    }
    CP_COMMIT();

    float pacc[16][4];
    #pragma unroll
    for (int t = 0; t < 16; t++) { pacc[t][0]=0.f; pacc[t][1]=0.f; pacc[t][2]=0.f; pacc[t][3]=0.f; }

    for (int h = 0; h < 2; h++) {
        for (int sp = 0; sp < 4; sp++) {
            int sidx = h * 4 + sp;
            if (sidx < 7) {
                int nidx = sidx + 1, nh2 = nidx >> 2, nsp = nidx & 3;
                for (int idx = tid; idx < 128 * 8; idx += NTH_A) {
                    int o = idx >> 3, u = idx & 7;
                    int csrc = (u < 4) ? (nsp * 32 + u * 8) : (128 + nsp * 32 + (u - 4) * 8);
                    cpasync16(&zb[nidx & 1][o * PJ_LD + u * 8],
                              &g_wprojb[(nh2 * 128 + o) * CC + csrc]);
                }
                CP_COMMIT();
                CP_WAIT1();
            } else {
                CP_WAIT0();
            }
            __syncthreads();
            uint32_t bPj = bPjP[sidx & 1];
            #pragma unroll
            for (int kt = 0; kt < 2; kt++) {
                int s = sp * 2 + kt;
                uint32_t a0 = pY[s][0], a1 = pY[s][1], a2 = pY[s][2], a3 = pY[s][3];
                #pragma unroll
                for (int p = 0; p < 8; p++) {
                    uint32_t b0, b1, b2, b3;
                    ldsm4(b0, b1, b2, b3, bPj + (p * 16 * PJ_LD + kt * 16) * 2);
                    mma16816(pacc[2*p],   a0, a1, a2, a3, b0, b1);
                    mma16816(pacc[2*p+1], a0, a1, a2, a3, b2, b3);
                }
            }
            __syncthreads();
        }

        // ---- epilogue for o-half h: merge cw partial sums in out_s (zone1), write ----
        // (h=0: prefetch of (h1,sp0) already in flight into zb0; out_s=zb1 is free)
        int r0 = rw * 16 + g, r1 = r0 + 8;
        if (cw == 0) {
            #pragma unroll
            for (int tl = 0; tl < 16; tl++) {
                int cc = tl * 8 + q * 2;
                out_s[r0 * 129 + cc]     = pacc[tl][0];
                out_s[r0 * 129 + cc + 1] = pacc[tl][1];
                out_s[r1 * 129 + cc]     = pacc[tl][2];
                out_s[r1 * 129 + cc + 1] = pacc[tl][3];
            }
        }
        __syncthreads();
        if (cw == 1) {
            #pragma unroll
            for (int tl = 0; tl < 16; tl++) {
                int cc = tl * 8 + q * 2;
                out_s[r0 * 129 + cc]     += pacc[tl][0];
                out_s[r0 * 129 + cc + 1] += pacc[tl][1];
                out_s[r1 * 129 + cc]     += pacc[tl][2];
                out_s[r1 * 129 + cc + 1] += pacc[tl][3];
            }
        }
        __syncthreads();
        if (evalid) {
            const float* os = out_s + nl * 129;
            #pragma unroll
            for (int it = 0; it < 32; it++) {
                int ol = ob + it * 4;
                size_t gi = ebase + (size_t)(h * 128 + ol) * (HH * HH);
                out[gi] = x[gi] + os[ol];
            }
        }
        __syncthreads();   // out_s reads done before zone1 reuse by next stage
        if (h == 0) {
            #pragma unroll
            for (int t = 0; t < 16; t++) { pacc[t][0]=0.f; pacc[t][1]=0.f; pacc[t][2]=0.f; pacc[t][3]=0.f; }
        }
    }
}

// ---------------- launch ----------------
extern "C" void kernel_launch(void* const* d_in, const int* in_sizes, int n_in,
                              void* d_out, int out_size) {
    const float* x     = (const float*)d_in[0];
    const float* wt    = (const float*)d_in[1];
    const float* wp    = (const float*)d_in[2];
    const float* wproj = (const float*)d_in[3];
    float* out = (float*)d_out;

    cudaFuncSetAttribute(embed_kernel, cudaFuncAttributeMaxDynamicSharedMemorySize, EMBED_SMEM);
    cudaFuncSetAttribute(attn_kernel,  cudaFuncAttributeMaxDynamicSharedMemorySize, ATTN_SMEM);

    embed_kernel<<<NWIN, NTH, EMBED_SMEM>>>(x, wt, wp, wproj);
    attn_kernel<<<NWIN * NBLK_E, NTH_A, ATTN_SMEM>>>(x, out);
}